// round 8
// baseline (speedup 1.0000x reference)
#include <cuda_runtime.h>
#include <cuda_fp16.h>
#include <math.h>
#include <stdint.h>

#define D     768
#define SEQ   4096
#define BATCH 4
#define NTOK  (BATCH * SEQ)
#define SCALE 0.03608439182435161f  // 1/sqrt(768)

// ---------------------------------------------------------------------------
// Device-global scratch
// ---------------------------------------------------------------------------
__device__ __align__(256) __half g_Xf[NTOK * D];
__device__ __align__(256) __half g_Wf[3 * D * D];
__device__ __align__(256) __half g_Qf[NTOK * D];
__device__ __align__(256) __half g_Kf[NTOK * D];
__device__ __align__(256) __half g_Vtf[NTOK * D];                 // [b][d][seq]
__device__ float g_S[(size_t)BATCH * SEQ * SEQ];                   // raw scaled scores
__device__ __align__(256) __half g_Pf[(size_t)BATCH * SEQ * SEQ];

// fp16 core: A tile 256x64, B tile 128x64, stride 72 (conflict-free ldmatrix)
#define FSTR     72
#define TILE_AB  (256 * FSTR * 2)        // 36864 B (A tile)
#define TILE_BB  (128 * FSTR * 2)        // 18432 B (B tile)
#define STAGE_F  (TILE_AB + TILE_BB)     // 55296
#define DYN_F    (2 * STAGE_F)           // 110592

// ---------------------------------------------------------------------------
// PTX helpers
// ---------------------------------------------------------------------------
__device__ __forceinline__ uint32_t smem_u32(const void* p) {
    uint32_t a;
    asm("{ .reg .u64 t; cvta.to.shared.u64 t, %1; cvt.u32.u64 %0, t; }" : "=r"(a) : "l"(p));
    return a;
}
__device__ __forceinline__ void ldsm4(uint32_t r[4], uint32_t addr) {
    asm volatile("ldmatrix.sync.aligned.m8n8.x4.shared.b16 {%0,%1,%2,%3}, [%4];"
                 : "=r"(r[0]), "=r"(r[1]), "=r"(r[2]), "=r"(r[3]) : "r"(addr));
}
__device__ __forceinline__ void mma_f16(float c[4], const uint32_t a[4],
                                        uint32_t b0, uint32_t b1) {
    asm volatile(
        "mma.sync.aligned.m16n8k16.row.col.f32.f16.f16.f32 "
        "{%0,%1,%2,%3}, {%4,%5,%6,%7}, {%8,%9}, {%0,%1,%2,%3};"
        : "+f"(c[0]), "+f"(c[1]), "+f"(c[2]), "+f"(c[3])
        : "r"(a[0]), "r"(a[1]), "r"(a[2]), "r"(a[3]), "r"(b0), "r"(b1));
}
#define CP16(dst, src) asm volatile("cp.async.cg.shared.global [%0], [%1], 16;" :: "r"(dst), "l"(src) : "memory")
#define CP_COMMIT()    asm volatile("cp.async.commit_group;" ::: "memory")
#define CP_WAIT0()     asm volatile("cp.async.wait_group 0;" ::: "memory")
#define CP_WAIT1()     asm volatile("cp.async.wait_group 1;" ::: "memory")

__device__ __forceinline__ unsigned short hfu(__half x) {
    return *reinterpret_cast<unsigned short*>(&x);
}
__device__ __forceinline__ uint32_t pack_h2(float v0, float v1) {
    return (uint32_t)hfu(__float2half_rn(v0)) | ((uint32_t)hfu(__float2half_rn(v1)) << 16);
}

// ===========================================================================
// fp16 256x128 GEMM core, 512 threads, K-chunk 64
// A[256,K] * B[128,K]^T. Warp w: rows (w>>1)*32..+31, cols (w&1)*64..+63.
// ===========================================================================
__device__ __forceinline__ void load_chunk_f(
    uint32_t stage,
    const __half* __restrict__ A, int lda,
    const __half* __restrict__ B, int ldb, int k0)
{
    const int t   = threadIdx.x;
    const int seg = t & 7;        // 16B segment of a 128B row
    const int r0  = t >> 3;       // 0..63
    // A: 256 rows
    #pragma unroll
    for (int i = 0; i < 4; i++) {
        const int row = r0 + i * 64;
        const uint32_t so = (uint32_t)(row * FSTR + seg * 8) * 2;
        CP16(stage + so, A + (size_t)row * lda + k0 + seg * 8);
    }
    // B: 128 rows
    #pragma unroll
    for (int i = 0; i < 2; i++) {
        const int row = r0 + i * 64;
        const uint32_t so = (uint32_t)(row * FSTR + seg * 8) * 2;
        CP16(stage + TILE_AB + so, B + (size_t)row * ldb + k0 + seg * 8);
    }
}

__device__ __forceinline__ void compute_chunk_f(
    uint32_t stage, const uint32_t offA[2], const uint32_t offB[4],
    float acc[2][8][4])
{
    const uint32_t aT = stage, bT = stage + TILE_AB;
    #pragma unroll
    for (int kk = 0; kk < 64; kk += 16) {
        uint32_t af[2][4];
        ldsm4(af[0], aT + offA[0] + kk * 2);
        ldsm4(af[1], aT + offA[1] + kk * 2);
        #pragma unroll
        for (int g = 0; g < 4; g++) {
            uint32_t bf[4];
            ldsm4(bf, bT + offB[g] + kk * 2);
            #pragma unroll
            for (int mt = 0; mt < 2; mt++) {
                #pragma unroll
                for (int nt = 0; nt < 2; nt++)
                    mma_f16(acc[mt][g * 2 + nt], af[mt], bf[nt * 2], bf[nt * 2 + 1]);
            }
        }
    }
}

__device__ __forceinline__ void gemm_run_f(
    const __half* __restrict__ A, int lda,
    const __half* __restrict__ B, int ldb,
    int nchunks, float acc[2][8][4])
{
    extern __shared__ char dsm[];
    const uint32_t base = smem_u32(dsm);
    const int lane = threadIdx.x & 31;
    const int warp = threadIdx.x >> 5;     // 0..15
    const int wm = warp >> 1, wn = warp & 1;
    const int rowA = ((lane >> 3) & 1) * 8 + (lane & 7);
    const int colA = (lane >> 4) * 8;
    const int rowB = (lane >> 4) * 8 + (lane & 7);
    const int colB = ((lane >> 3) & 1) * 8;

    uint32_t offA[2], offB[4];
    #pragma unroll
    for (int mt = 0; mt < 2; mt++)
        offA[mt] = ((wm * 32 + mt * 16 + rowA) * FSTR + colA) * 2;
    #pragma unroll
    for (int g = 0; g < 4; g++)
        offB[g] = ((wn * 64 + g * 16 + rowB) * FSTR + colB) * 2;

    load_chunk_f(base, A, lda, B, ldb, 0);
    CP_COMMIT();
    for (int c = 0; c < nchunks; c++) {
        if (c + 1 < nchunks) {
            load_chunk_f(base + ((c + 1) & 1) * STAGE_F, A, lda, B, ldb, (c + 1) * 64);
            CP_COMMIT();
            CP_WAIT1();
        } else {
            CP_WAIT0();
        }
        __syncthreads();
        compute_chunk_f(base + (c & 1) * STAGE_F, offA, offB, acc);
        __syncthreads();
    }
}

// ===========================================================================
// Epilogues (256x128 tile, 16 warps in 8x2)
// ===========================================================================
__device__ __forceinline__ void store_f32_t(
    float* __restrict__ C, size_t ldc, int row0, int col0,
    const float acc[2][8][4], float scale)
{
    const int lane = threadIdx.x & 31;
    const int warp = threadIdx.x >> 5;
    const int wm = warp >> 1, wn = warp & 1;
    #pragma unroll
    for (int mt = 0; mt < 2; mt++) {
        const int r = row0 + wm * 32 + mt * 16 + (lane >> 2);
        #pragma unroll
        for (int j = 0; j < 8; j++) {
            const int c = col0 + wn * 64 + j * 8 + (lane & 3) * 2;
            *(float2*)(C + (size_t)r * ldc + c) =
                make_float2(acc[mt][j][0] * scale, acc[mt][j][1] * scale);
            *(float2*)(C + (size_t)(r + 8) * ldc + c) =
                make_float2(acc[mt][j][2] * scale, acc[mt][j][3] * scale);
        }
    }
}

__device__ __forceinline__ void store_f16_t(
    __half* __restrict__ Cf, size_t ldc, int row0, int col0,
    const float acc[2][8][4])
{
    const int lane = threadIdx.x & 31;
    const int warp = threadIdx.x >> 5;
    const int wm = warp >> 1, wn = warp & 1;
    #pragma unroll
    for (int mt = 0; mt < 2; mt++) {
        const int r = row0 + wm * 32 + mt * 16 + (lane >> 2);
        #pragma unroll
        for (int j = 0; j < 8; j++) {
            const int c = col0 + wn * 64 + j * 8 + (lane & 3) * 2;
            *(uint32_t*)(Cf + (size_t)r * ldc + c)       = pack_h2(acc[mt][j][0], acc[mt][j][1]);
            *(uint32_t*)(Cf + (size_t)(r + 8) * ldc + c) = pack_h2(acc[mt][j][2], acc[mt][j][3]);
        }
    }
}

// Transposed fp16 V store via smem (256 seq x 128 d tile)
#define VT_STRIDE 136
__device__ __forceinline__ void store_vt_f16(int row0, int col0, const float acc[2][8][4])
{
    extern __shared__ char dsm[];
    unsigned short* sp = (unsigned short*)dsm;   // 256 x VT_STRIDE
    const int tid  = threadIdx.x;
    const int lane = tid & 31;
    const int warp = tid >> 5;
    const int wm = warp >> 1, wn = warp & 1;

    __syncthreads();
    #pragma unroll
    for (int mt = 0; mt < 2; mt++) {
        const int r = wm * 32 + mt * 16 + (lane >> 2);
        #pragma unroll
        for (int j = 0; j < 8; j++) {
            const int c = wn * 64 + j * 8 + (lane & 3) * 2;
            #pragma unroll
            for (int e = 0; e < 4; e++)
                sp[(r + (e >> 1) * 8) * VT_STRIDE + c + (e & 1)] =
                    hfu(__float2half_rn(acc[mt][j][e]));
        }
    }
    __syncthreads();

    const int b   = row0 >> 12;
    const int rin = row0 & (SEQ - 1);
    const int d   = tid >> 2;            // 0..127
    const int ks  = (tid & 3) * 64;      // seq quarter
    __half* dst = g_Vtf + (size_t)b * D * SEQ + (size_t)(col0 + d) * SEQ + rin + ks;
    #pragma unroll
    for (int g = 0; g < 8; g++) {
        uint32_t w[4];
        #pragma unroll
        for (int h = 0; h < 4; h++) {
            uint32_t a0 = sp[(ks + g * 8 + h * 2) * VT_STRIDE + d];
            uint32_t a1 = sp[(ks + g * 8 + h * 2 + 1) * VT_STRIDE + d];
            w[h] = a0 | (a1 << 16);
        }
        *(uint4*)(dst + g * 8) = make_uint4(w[0], w[1], w[2], w[3]);
    }
}

// ===========================================================================
// Kernels
// ===========================================================================
__global__ void __launch_bounds__(256) cvt_kernel(const float* __restrict__ src,
                                                  __half* __restrict__ dst, int n)
{
    int i = (blockIdx.x * 256 + threadIdx.x) * 8;
    if (i >= n) return;
    float4 v0 = *(const float4*)(src + i);
    float4 v1 = *(const float4*)(src + i + 4);
    *(uint4*)(dst + i) = make_uint4(pack_h2(v0.x, v0.y), pack_h2(v0.z, v0.w),
                                    pack_h2(v1.x, v1.y), pack_h2(v1.z, v1.w));
}

__global__ void __launch_bounds__(512, 1) qkv_mm()
{
    const int z    = blockIdx.z;
    const int row0 = blockIdx.y * 256;
    const int col0 = blockIdx.x * 128;

    float acc[2][8][4] = {};
    gemm_run_f(g_Xf + (size_t)row0 * D, D,
               g_Wf + (size_t)z * D * D + (size_t)col0 * D, D, D / 64, acc);

    if (z == 0)      store_f16_t(g_Qf, D, row0, col0, acc);
    else if (z == 1) store_f16_t(g_Kf, D, row0, col0, acc);
    else             store_vt_f16(row0, col0, acc);
}

// Triangular tiling over 256-row x 128-col tiles: for by2 in [0,16),
// bx in [0, 2*by2+2). Linear index t in [0, 272): by2^2+by2 <= t.
__global__ void __launch_bounds__(512, 1) scores_mm()
{
    const int t = blockIdx.x;
    int by2 = (int)((sqrtf(4.0f * t + 1.0f) - 1.0f) * 0.5f);
    while ((by2 + 1) * (by2 + 2) <= t) by2++;
    while (by2 * (by2 + 1) > t) by2--;
    const int bx = t - by2 * (by2 + 1);
    const int b  = blockIdx.y;
    const int row0 = by2 * 256, col0 = bx * 128;
    const size_t qoff = (size_t)b * SEQ * D;

    float acc[2][8][4] = {};
    gemm_run_f(g_Qf + qoff + (size_t)row0 * D, D,
               g_Kf + qoff + (size_t)col0 * D, D, D / 64, acc);
    store_f32_t(g_S + (size_t)b * SEQ * SEQ, SEQ, row0, col0, acc, SCALE);
}

// Single-pass causal softmax; writes fp16 P zero-filled to 128 boundary.
__global__ void __launch_bounds__(256) softmax_kernel()
{
    __shared__ float srow[SEQ];
    __shared__ float red[256];
    const int q = blockIdx.x;
    const int b = blockIdx.y;
    const float* row = g_S + (size_t)b * SEQ * SEQ + (size_t)q * SEQ;
    const int len  = q + 1;
    const int wlen = ((q >> 7) + 1) << 7;
    const int tid  = threadIdx.x;

    float m = -INFINITY;
    for (int i = tid; i < len; i += 256) {
        float v = row[i];
        srow[i] = v;
        m = fmaxf(m, v);
    }
    red[tid] = m; __syncthreads();
    #pragma unroll
    for (int s = 128; s > 0; s >>= 1) {
        if (tid < s) red[tid] = fmaxf(red[tid], red[tid + s]);
        __syncthreads();
    }
    m = red[0]; __syncthreads();

    float sum = 0.0f;
    for (int i = tid; i < len; i += 256) {
        float e = __expf(srow[i] - m);
        srow[i] = e;
        sum += e;
    }
    red[tid] = sum; __syncthreads();
    #pragma unroll
    for (int s = 128; s > 0; s >>= 1) {
        if (tid < s) red[tid] += red[tid + s];
        __syncthreads();
    }
    const float inv = 1.0f / red[0];
    __syncthreads();

    __half* pf = g_Pf + (size_t)b * SEQ * SEQ + (size_t)q * SEQ;
    for (int i = tid; i < wlen; i += 256)
        pf[i] = (i < len) ? __float2half_rn(srow[i] * inv) : __float2half_rn(0.0f);
}

__global__ void __launch_bounds__(512, 1) pv_mm(float* __restrict__ Out)
{
    const int b    = blockIdx.z;
    const int by2  = (gridDim.y - 1) - blockIdx.y;   // heavy row-tiles first
    const int row0 = by2 * 256;
    const int col0 = blockIdx.x * 128;
    const int nchunks = (by2 + 1) * 4;               // Klim=(by2+1)*256, K64 chunks

    const size_t poff = (size_t)b * SEQ * SEQ + (size_t)row0 * SEQ;
    const size_t voff = (size_t)b * D * SEQ + (size_t)col0 * SEQ;

    float acc[2][8][4] = {};
    gemm_run_f(g_Pf + poff, SEQ, g_Vtf + voff, SEQ, nchunks, acc);
    store_f32_t(Out + (size_t)b * SEQ * D, D, row0, col0, acc, 1.0f);
}

// ---------------------------------------------------------------------------
extern "C" void kernel_launch(void* const* d_in, const int* in_sizes, int n_in,
                              void* d_out, int out_size)
{
    const float* X  = (const float*)d_in[0];
    const float* Wq = (const float*)d_in[1];
    const float* Wk = (const float*)d_in[2];
    const float* Wv = (const float*)d_in[3];
    float* Out = (float*)d_out;

    cudaFuncSetAttribute(qkv_mm,    cudaFuncAttributeMaxDynamicSharedMemorySize, DYN_F);
    cudaFuncSetAttribute(scores_mm, cudaFuncAttributeMaxDynamicSharedMemorySize, DYN_F);
    cudaFuncSetAttribute(pv_mm,     cudaFuncAttributeMaxDynamicSharedMemorySize, DYN_F);

    __half *xf, *wf;
    cudaGetSymbolAddress((void**)&xf, g_Xf);
    cudaGetSymbolAddress((void**)&wf, g_Wf);

    cvt_kernel<<<(NTOK * D) / 2048, 256>>>(X, xf, NTOK * D);
    cvt_kernel<<<(D * D) / 2048, 256>>>(Wq, wf + 0 * D * D, D * D);
    cvt_kernel<<<(D * D) / 2048, 256>>>(Wk, wf + 1 * D * D, D * D);
    cvt_kernel<<<(D * D) / 2048, 256>>>(Wv, wf + 2 * D * D, D * D);

    qkv_mm<<<dim3(D / 128, NTOK / 256, 3), 512, DYN_F>>>();
    scores_mm<<<dim3(272, BATCH), 512, DYN_F>>>();
    softmax_kernel<<<dim3(SEQ, BATCH), 256>>>();
    pv_mm<<<dim3(D / 128, SEQ / 256, BATCH), 512, DYN_F>>>(Out);
}

// round 9
// speedup vs baseline: 1.1744x; 1.1744x over previous
#include <cuda_runtime.h>
#include <cuda_fp16.h>
#include <math.h>
#include <stdint.h>

#define D     768
#define SEQ   4096
#define BATCH 4
#define NTOK  (BATCH * SEQ)
#define SCALE 0.03608439182435161f  // 1/sqrt(768)

// ---------------------------------------------------------------------------
// Device-global scratch
// ---------------------------------------------------------------------------
__device__ __align__(256) __half g_Xf[NTOK * D];
__device__ __align__(256) __half g_Wf[3 * D * D];
__device__ __align__(256) __half g_Qf[NTOK * D];    // pre-scaled by SCALE
__device__ __align__(256) __half g_Kf[NTOK * D];
__device__ __align__(256) __half g_Vtf[NTOK * D];                 // [b][d][seq]
__device__ float g_S[(size_t)BATCH * SEQ * SEQ];                   // scaled scores
__device__ __align__(256) __half g_Pf[(size_t)BATCH * SEQ * SEQ];

// fp16 core: 128x64 tiles, stride 72 (144B rows, conflict-free ldmatrix)
#define FSTR     72
#define TILE_F   (128 * FSTR * 2)        // 18432 B
#define STAGE_F  (2 * TILE_F)            // A|B = 36864
#define NSTAGE   3
#define DYN_F    (NSTAGE * STAGE_F)      // 110592 (2 CTAs/SM: 221184 <= 228KB)

// ---------------------------------------------------------------------------
// PTX helpers
// ---------------------------------------------------------------------------
__device__ __forceinline__ uint32_t smem_u32(const void* p) {
    uint32_t a;
    asm("{ .reg .u64 t; cvta.to.shared.u64 t, %1; cvt.u32.u64 %0, t; }" : "=r"(a) : "l"(p));
    return a;
}
__device__ __forceinline__ void ldsm4(uint32_t r[4], uint32_t addr) {
    asm volatile("ldmatrix.sync.aligned.m8n8.x4.shared.b16 {%0,%1,%2,%3}, [%4];"
                 : "=r"(r[0]), "=r"(r[1]), "=r"(r[2]), "=r"(r[3]) : "r"(addr));
}
__device__ __forceinline__ void mma_f16(float c[4], const uint32_t a[4],
                                        uint32_t b0, uint32_t b1) {
    asm volatile(
        "mma.sync.aligned.m16n8k16.row.col.f32.f16.f16.f32 "
        "{%0,%1,%2,%3}, {%4,%5,%6,%7}, {%8,%9}, {%0,%1,%2,%3};"
        : "+f"(c[0]), "+f"(c[1]), "+f"(c[2]), "+f"(c[3])
        : "r"(a[0]), "r"(a[1]), "r"(a[2]), "r"(a[3]), "r"(b0), "r"(b1));
}
#define CP16(dst, src) asm volatile("cp.async.cg.shared.global [%0], [%1], 16;" :: "r"(dst), "l"(src) : "memory")
#define CP_COMMIT()    asm volatile("cp.async.commit_group;" ::: "memory")
#define CP_WAIT0()     asm volatile("cp.async.wait_group 0;" ::: "memory")
#define CP_WAIT1()     asm volatile("cp.async.wait_group 1;" ::: "memory")

__device__ __forceinline__ unsigned short hfu(__half x) {
    return *reinterpret_cast<unsigned short*>(&x);
}
__device__ __forceinline__ uint32_t pack_h2(float v0, float v1) {
    return (uint32_t)hfu(__float2half_rn(v0)) | ((uint32_t)hfu(__float2half_rn(v1)) << 16);
}

// ===========================================================================
// fp16 single-mma 128x128 GEMM core, 256 threads, K-chunk 64, 3-stage pipe
// ===========================================================================
__device__ __forceinline__ void load_chunk_f(
    uint32_t stage,
    const __half* __restrict__ A, int lda,
    const __half* __restrict__ B, int ldb, int k0)
{
    const int t   = threadIdx.x;
    const int seg = t & 7;        // 16B segment of a 128B row (64 f16)
    const int r0  = t >> 3;       // 0..31
    #pragma unroll
    for (int i = 0; i < 4; i++) {
        const int row = r0 + i * 32;
        const uint32_t so = (uint32_t)(row * FSTR + seg * 8) * 2;
        CP16(stage + so,          A + (size_t)row * lda + k0 + seg * 8);
        CP16(stage + TILE_F + so, B + (size_t)row * ldb + k0 + seg * 8);
    }
}

__device__ __forceinline__ void compute_chunk_f(
    uint32_t stage, const uint32_t offA[2], const uint32_t offB[4],
    float acc[2][8][4])
{
    const uint32_t aT = stage, bT = stage + TILE_F;
    #pragma unroll
    for (int kk = 0; kk < 64; kk += 16) {
        uint32_t af[2][4];
        ldsm4(af[0], aT + offA[0] + kk * 2);
        ldsm4(af[1], aT + offA[1] + kk * 2);
        #pragma unroll
        for (int g = 0; g < 4; g++) {
            uint32_t bf[4];
            ldsm4(bf, bT + offB[g] + kk * 2);
            #pragma unroll
            for (int mt = 0; mt < 2; mt++) {
                #pragma unroll
                for (int nt = 0; nt < 2; nt++)
                    mma_f16(acc[mt][g * 2 + nt], af[mt], bf[nt * 2], bf[nt * 2 + 1]);
            }
        }
    }
}

__device__ __forceinline__ void gemm_run_f(
    const __half* __restrict__ A, int lda,
    const __half* __restrict__ B, int ldb,
    int nchunks, float acc[2][8][4])
{
    extern __shared__ char dsm[];
    const uint32_t base = smem_u32(dsm);
    const int lane = threadIdx.x & 31;
    const int warp = threadIdx.x >> 5;
    const int wm = warp >> 1, wn = warp & 1;
    const int rowA = ((lane >> 3) & 1) * 8 + (lane & 7);
    const int colA = (lane >> 4) * 8;
    const int rowB = (lane >> 4) * 8 + (lane & 7);
    const int colB = ((lane >> 3) & 1) * 8;

    uint32_t offA[2], offB[4];
    #pragma unroll
    for (int mt = 0; mt < 2; mt++)
        offA[mt] = ((wm * 32 + mt * 16 + rowA) * FSTR + colA) * 2;
    #pragma unroll
    for (int g = 0; g < 4; g++)
        offB[g] = ((wn * 64 + g * 16 + rowB) * FSTR + colB) * 2;

    // Prologue: stages 0 and 1 in flight
    load_chunk_f(base, A, lda, B, ldb, 0);
    CP_COMMIT();
    if (nchunks > 1) {
        load_chunk_f(base + STAGE_F, A, lda, B, ldb, 64);
        CP_COMMIT();
    }

    int s = 0;                       // stage of chunk c
    for (int c = 0; c < nchunks; c++) {
        if (c + 1 < nchunks) CP_WAIT1(); else CP_WAIT0();
        __syncthreads();             // publish chunk c; all warps done chunk c-1
        if (c + 2 < nchunks) {
            int s2 = s + 2; if (s2 >= NSTAGE) s2 -= NSTAGE;
            load_chunk_f(base + s2 * STAGE_F, A, lda, B, ldb, (c + 2) * 64);
            CP_COMMIT();
        }
        compute_chunk_f(base + s * STAGE_F, offA, offB, acc);
        if (++s == NSTAGE) s = 0;
    }
    __syncthreads();                 // protect smem reuse by epilogue (vt)
}

// ===========================================================================
// Epilogues (128x128, 8-warp 2x2 layout)
// ===========================================================================
__device__ __forceinline__ void store_f32_t(
    float* __restrict__ C, size_t ldc, int row0, int col0,
    const float acc[2][8][4])
{
    const int lane = threadIdx.x & 31;
    const int warp = threadIdx.x >> 5;
    const int wm = warp >> 1, wn = warp & 1;
    #pragma unroll
    for (int mt = 0; mt < 2; mt++) {
        const int r = row0 + wm * 32 + mt * 16 + (lane >> 2);
        #pragma unroll
        for (int j = 0; j < 8; j++) {
            const int c = col0 + wn * 64 + j * 8 + (lane & 3) * 2;
            *(float2*)(C + (size_t)r * ldc + c) =
                make_float2(acc[mt][j][0], acc[mt][j][1]);
            *(float2*)(C + (size_t)(r + 8) * ldc + c) =
                make_float2(acc[mt][j][2], acc[mt][j][3]);
        }
    }
}

__device__ __forceinline__ void store_f16_t(
    __half* __restrict__ Cf, size_t ldc, int row0, int col0,
    const float acc[2][8][4], float scale)
{
    const int lane = threadIdx.x & 31;
    const int warp = threadIdx.x >> 5;
    const int wm = warp >> 1, wn = warp & 1;
    #pragma unroll
    for (int mt = 0; mt < 2; mt++) {
        const int r = row0 + wm * 32 + mt * 16 + (lane >> 2);
        #pragma unroll
        for (int j = 0; j < 8; j++) {
            const int c = col0 + wn * 64 + j * 8 + (lane & 3) * 2;
            *(uint32_t*)(Cf + (size_t)r * ldc + c) =
                pack_h2(acc[mt][j][0] * scale, acc[mt][j][1] * scale);
            *(uint32_t*)(Cf + (size_t)(r + 8) * ldc + c) =
                pack_h2(acc[mt][j][2] * scale, acc[mt][j][3] * scale);
        }
    }
}

// Transposed fp16 V store via smem (128x128 tile)
#define VT_STRIDE 136
__device__ __forceinline__ void store_vt_f16(int row0, int col0, const float acc[2][8][4])
{
    extern __shared__ char dsm[];
    unsigned short* sp = (unsigned short*)dsm;
    const int tid  = threadIdx.x;
    const int lane = tid & 31;
    const int warp = tid >> 5;
    const int wm = warp >> 1, wn = warp & 1;

    #pragma unroll
    for (int mt = 0; mt < 2; mt++) {
        const int r = wm * 32 + mt * 16 + (lane >> 2);
        #pragma unroll
        for (int j = 0; j < 8; j++) {
            const int c = wn * 64 + j * 8 + (lane & 3) * 2;
            #pragma unroll
            for (int e = 0; e < 4; e++)
                sp[(r + (e >> 1) * 8) * VT_STRIDE + c + (e & 1)] =
                    hfu(__float2half_rn(acc[mt][j][e]));
        }
    }
    __syncthreads();

    const int b   = row0 >> 12;
    const int rin = row0 & (SEQ - 1);
    const int d   = tid >> 1;
    const int ks  = (tid & 1) * 64;
    __half* dst = g_Vtf + (size_t)b * D * SEQ + (size_t)(col0 + d) * SEQ + rin + ks;
    #pragma unroll
    for (int g = 0; g < 8; g++) {
        uint32_t w[4];
        #pragma unroll
        for (int h = 0; h < 4; h++) {
            uint32_t a0 = sp[(ks + g * 8 + h * 2) * VT_STRIDE + d];
            uint32_t a1 = sp[(ks + g * 8 + h * 2 + 1) * VT_STRIDE + d];
            w[h] = a0 | (a1 << 16);
        }
        *(uint4*)(dst + g * 8) = make_uint4(w[0], w[1], w[2], w[3]);
    }
}

// ===========================================================================
// Kernels
// ===========================================================================
__global__ void __launch_bounds__(256) cvt_kernel(const float* __restrict__ src,
                                                  __half* __restrict__ dst, int n)
{
    int i = (blockIdx.x * 256 + threadIdx.x) * 8;
    if (i >= n) return;
    float4 v0 = *(const float4*)(src + i);
    float4 v1 = *(const float4*)(src + i + 4);
    *(uint4*)(dst + i) = make_uint4(pack_h2(v0.x, v0.y), pack_h2(v0.z, v0.w),
                                    pack_h2(v1.x, v1.y), pack_h2(v1.z, v1.w));
}

__global__ void __launch_bounds__(256, 2) qkv_mm()
{
    const int z    = blockIdx.z;
    const int row0 = blockIdx.y * 128;
    const int col0 = blockIdx.x * 128;

    float acc[2][8][4] = {};
    gemm_run_f(g_Xf + (size_t)row0 * D, D,
               g_Wf + (size_t)z * D * D + (size_t)col0 * D, D, D / 64, acc);

    if (z == 0)      store_f16_t(g_Qf, D, row0, col0, acc, SCALE);
    else if (z == 1) store_f16_t(g_Kf, D, row0, col0, acc, 1.0f);
    else             store_vt_f16(row0, col0, acc);
}

__global__ void __launch_bounds__(256, 2) scores_mm()
{
    const int t = blockIdx.x;
    int by = (int)((sqrtf(8.0f * t + 1.0f) - 1.0f) * 0.5f);
    while ((by + 1) * (by + 2) / 2 <= t) by++;
    while (by * (by + 1) / 2 > t) by--;
    const int bx = t - by * (by + 1) / 2;
    const int b  = blockIdx.y;
    const int row0 = by * 128, col0 = bx * 128;
    const size_t qoff = (size_t)b * SEQ * D;

    float acc[2][8][4] = {};
    gemm_run_f(g_Qf + qoff + (size_t)row0 * D, D,
               g_Kf + qoff + (size_t)col0 * D, D, D / 64, acc);
    store_f32_t(g_S + (size_t)b * SEQ * SEQ, SEQ, row0, col0, acc);
}

// Single-pass causal softmax; writes fp16 P zero-filled to 128 boundary.
__global__ void __launch_bounds__(256) softmax_kernel()
{
    __shared__ float srow[SEQ];
    __shared__ float red[256];
    const int q = blockIdx.x;
    const int b = blockIdx.y;
    const float* row = g_S + (size_t)b * SEQ * SEQ + (size_t)q * SEQ;
    const int len  = q + 1;
    const int wlen = ((q >> 7) + 1) << 7;
    const int tid  = threadIdx.x;

    float m = -INFINITY;
    for (int i = tid; i < len; i += 256) {
        float v = row[i];
        srow[i] = v;
        m = fmaxf(m, v);
    }
    red[tid] = m; __syncthreads();
    #pragma unroll
    for (int s = 128; s > 0; s >>= 1) {
        if (tid < s) red[tid] = fmaxf(red[tid], red[tid + s]);
        __syncthreads();
    }
    m = red[0]; __syncthreads();

    float sum = 0.0f;
    for (int i = tid; i < len; i += 256) {
        float e = __expf(srow[i] - m);
        srow[i] = e;
        sum += e;
    }
    red[tid] = sum; __syncthreads();
    #pragma unroll
    for (int s = 128; s > 0; s >>= 1) {
        if (tid < s) red[tid] += red[tid + s];
        __syncthreads();
    }
    const float inv = 1.0f / red[0];
    __syncthreads();

    __half* pf = g_Pf + (size_t)b * SEQ * SEQ + (size_t)q * SEQ;
    for (int i = tid; i < wlen; i += 256)
        pf[i] = (i < len) ? __float2half_rn(srow[i] * inv) : __float2half_rn(0.0f);
}

__global__ void __launch_bounds__(256, 2) pv_mm(float* __restrict__ Out)
{
    const int b    = blockIdx.z;
    const int by   = (gridDim.y - 1) - blockIdx.y;   // heavy rows first
    const int row0 = by * 128;
    const int col0 = blockIdx.x * 128;
    const int nchunks = (by + 1) * 2;                // Klim / 64

    const size_t poff = (size_t)b * SEQ * SEQ + (size_t)row0 * SEQ;
    const size_t voff = (size_t)b * D * SEQ + (size_t)col0 * SEQ;

    float acc[2][8][4] = {};
    gemm_run_f(g_Pf + poff, SEQ, g_Vtf + voff, SEQ, nchunks, acc);
    store_f32_t(Out + (size_t)b * SEQ * D, D, row0, col0, acc);
}

// ---------------------------------------------------------------------------
extern "C" void kernel_launch(void* const* d_in, const int* in_sizes, int n_in,
                              void* d_out, int out_size)
{
    const float* X  = (const float*)d_in[0];
    const float* Wq = (const float*)d_in[1];
    const float* Wk = (const float*)d_in[2];
    const float* Wv = (const float*)d_in[3];
    float* Out = (float*)d_out;

    cudaFuncSetAttribute(qkv_mm,    cudaFuncAttributeMaxDynamicSharedMemorySize, DYN_F);
    cudaFuncSetAttribute(scores_mm, cudaFuncAttributeMaxDynamicSharedMemorySize, DYN_F);
    cudaFuncSetAttribute(pv_mm,     cudaFuncAttributeMaxDynamicSharedMemorySize, DYN_F);

    __half *xf, *wf;
    cudaGetSymbolAddress((void**)&xf, g_Xf);
    cudaGetSymbolAddress((void**)&wf, g_Wf);

    cvt_kernel<<<(NTOK * D) / 2048, 256>>>(X, xf, NTOK * D);
    cvt_kernel<<<(D * D) / 2048, 256>>>(Wq, wf + 0 * D * D, D * D);
    cvt_kernel<<<(D * D) / 2048, 256>>>(Wk, wf + 1 * D * D, D * D);
    cvt_kernel<<<(D * D) / 2048, 256>>>(Wv, wf + 2 * D * D, D * D);

    qkv_mm<<<dim3(D / 128, NTOK / 128, 3), 256, DYN_F>>>();
    scores_mm<<<dim3(528, BATCH), 256, DYN_F>>>();
    softmax_kernel<<<dim3(SEQ, BATCH), 256>>>();
    pv_mm<<<dim3(D / 128, SEQ / 128, BATCH), 256, DYN_F>>>(Out);
}

// round 10
// speedup vs baseline: 1.1784x; 1.0034x over previous
#include <cuda_runtime.h>
#include <cuda_fp16.h>
#include <math.h>
#include <stdint.h>

#define D     768
#define SEQ   4096
#define BATCH 4
#define NTOK  (BATCH * SEQ)
#define SCALE 0.03608439182435161f  // 1/sqrt(768)

// ---------------------------------------------------------------------------
// Device-global scratch
// ---------------------------------------------------------------------------
__device__ __align__(256) __half g_Xf[NTOK * D];
__device__ __align__(256) __half g_Wf[3 * D * D];
__device__ __align__(256) __half g_Qf[NTOK * D];    // pre-scaled by SCALE
__device__ __align__(256) __half g_Kf[NTOK * D];
__device__ __align__(256) __half g_Vtf[NTOK * D];                 // [b][d][seq]
__device__ float g_S[(size_t)BATCH * SEQ * SEQ];                   // scaled scores
__device__ __align__(256) __half g_Pf[(size_t)BATCH * SEQ * SEQ];

// fp16 core: 128x64 tiles, stride 72 (144B rows, conflict-free ldmatrix)
#define FSTR     72
#define TILE_F   (128 * FSTR * 2)        // 18432 B
#define STAGE_F  (2 * TILE_F)            // A|B = 36864
#define NSTAGE   3
#define DYN_F    (NSTAGE * STAGE_F)      // 110592 (2 CTAs/SM)

// ---------------------------------------------------------------------------
// PTX helpers
// ---------------------------------------------------------------------------
__device__ __forceinline__ uint32_t smem_u32(const void* p) {
    uint32_t a;
    asm("{ .reg .u64 t; cvta.to.shared.u64 t, %1; cvt.u32.u64 %0, t; }" : "=r"(a) : "l"(p));
    return a;
}
__device__ __forceinline__ void ldsm4(uint32_t r[4], uint32_t addr) {
    asm volatile("ldmatrix.sync.aligned.m8n8.x4.shared.b16 {%0,%1,%2,%3}, [%4];"
                 : "=r"(r[0]), "=r"(r[1]), "=r"(r[2]), "=r"(r[3]) : "r"(addr));
}
__device__ __forceinline__ void mma_f16(float c[4], const uint32_t a[4],
                                        uint32_t b0, uint32_t b1) {
    asm volatile(
        "mma.sync.aligned.m16n8k16.row.col.f32.f16.f16.f32 "
        "{%0,%1,%2,%3}, {%4,%5,%6,%7}, {%8,%9}, {%0,%1,%2,%3};"
        : "+f"(c[0]), "+f"(c[1]), "+f"(c[2]), "+f"(c[3])
        : "r"(a[0]), "r"(a[1]), "r"(a[2]), "r"(a[3]), "r"(b0), "r"(b1));
}
#define CP16(dst, src) asm volatile("cp.async.cg.shared.global [%0], [%1], 16;" :: "r"(dst), "l"(src) : "memory")
#define CP_COMMIT()    asm volatile("cp.async.commit_group;" ::: "memory")
#define CP_WAIT0()     asm volatile("cp.async.wait_group 0;" ::: "memory")
#define CP_WAIT1()     asm volatile("cp.async.wait_group 1;" ::: "memory")

__device__ __forceinline__ unsigned short hfu(__half x) {
    return *reinterpret_cast<unsigned short*>(&x);
}
__device__ __forceinline__ uint32_t pack_h2(float v0, float v1) {
    return (uint32_t)hfu(__float2half_rn(v0)) | ((uint32_t)hfu(__float2half_rn(v1)) << 16);
}

// ===========================================================================
// fp16 single-mma 128x128 GEMM core, 256 threads, K-chunk 64, 3-stage pipe
// ===========================================================================
__device__ __forceinline__ void load_chunk_f(
    uint32_t stage,
    const __half* __restrict__ A, int lda,
    const __half* __restrict__ B, int ldb, int k0)
{
    const int t   = threadIdx.x;
    const int seg = t & 7;        // 16B segment of a 128B row (64 f16)
    const int r0  = t >> 3;       // 0..31
    #pragma unroll
    for (int i = 0; i < 4; i++) {
        const int row = r0 + i * 32;
        const uint32_t so = (uint32_t)(row * FSTR + seg * 8) * 2;
        CP16(stage + so,          A + (size_t)row * lda + k0 + seg * 8);
        CP16(stage + TILE_F + so, B + (size_t)row * ldb + k0 + seg * 8);
    }
}

__device__ __forceinline__ void compute_chunk_f(
    uint32_t stage, const uint32_t offA[2], const uint32_t offB[4],
    float acc[2][8][4])
{
    const uint32_t aT = stage, bT = stage + TILE_F;
    #pragma unroll
    for (int kk = 0; kk < 64; kk += 16) {
        uint32_t af[2][4];
        ldsm4(af[0], aT + offA[0] + kk * 2);
        ldsm4(af[1], aT + offA[1] + kk * 2);
        #pragma unroll
        for (int g = 0; g < 4; g++) {
            uint32_t bf[4];
            ldsm4(bf, bT + offB[g] + kk * 2);
            #pragma unroll
            for (int mt = 0; mt < 2; mt++) {
                #pragma unroll
                for (int nt = 0; nt < 2; nt++)
                    mma_f16(acc[mt][g * 2 + nt], af[mt], bf[nt * 2], bf[nt * 2 + 1]);
            }
        }
    }
}

__device__ __forceinline__ void gemm_run_f(
    const __half* __restrict__ A, int lda,
    const __half* __restrict__ B, int ldb,
    int nchunks, float acc[2][8][4])
{
    extern __shared__ char dsm[];
    const uint32_t base = smem_u32(dsm);
    const int lane = threadIdx.x & 31;
    const int warp = threadIdx.x >> 5;
    const int wm = warp >> 1, wn = warp & 1;
    const int rowA = ((lane >> 3) & 1) * 8 + (lane & 7);
    const int colA = (lane >> 4) * 8;
    const int rowB = (lane >> 4) * 8 + (lane & 7);
    const int colB = ((lane >> 3) & 1) * 8;

    uint32_t offA[2], offB[4];
    #pragma unroll
    for (int mt = 0; mt < 2; mt++)
        offA[mt] = ((wm * 32 + mt * 16 + rowA) * FSTR + colA) * 2;
    #pragma unroll
    for (int g = 0; g < 4; g++)
        offB[g] = ((wn * 64 + g * 16 + rowB) * FSTR + colB) * 2;

    // Prologue: stages 0 and 1 in flight
    load_chunk_f(base, A, lda, B, ldb, 0);
    CP_COMMIT();
    if (nchunks > 1) {
        load_chunk_f(base + STAGE_F, A, lda, B, ldb, 64);
        CP_COMMIT();
    }

    int s = 0;
    for (int c = 0; c < nchunks; c++) {
        if (c + 1 < nchunks) CP_WAIT1(); else CP_WAIT0();
        __syncthreads();
        if (c + 2 < nchunks) {
            int s2 = s + 2; if (s2 >= NSTAGE) s2 -= NSTAGE;
            load_chunk_f(base + s2 * STAGE_F, A, lda, B, ldb, (c + 2) * 64);
            CP_COMMIT();
        }
        compute_chunk_f(base + s * STAGE_F, offA, offB, acc);
        if (++s == NSTAGE) s = 0;
    }
    __syncthreads();
}

// ===========================================================================
// Epilogues (128x128, 8-warp 2x2 layout)
// ===========================================================================
__device__ __forceinline__ void store_f32_t(
    float* __restrict__ C, size_t ldc, int row0, int col0,
    const float acc[2][8][4])
{
    const int lane = threadIdx.x & 31;
    const int warp = threadIdx.x >> 5;
    const int wm = warp >> 1, wn = warp & 1;
    #pragma unroll
    for (int mt = 0; mt < 2; mt++) {
        const int r = row0 + wm * 32 + mt * 16 + (lane >> 2);
        #pragma unroll
        for (int j = 0; j < 8; j++) {
            const int c = col0 + wn * 64 + j * 8 + (lane & 3) * 2;
            *(float2*)(C + (size_t)r * ldc + c) =
                make_float2(acc[mt][j][0], acc[mt][j][1]);
            *(float2*)(C + (size_t)(r + 8) * ldc + c) =
                make_float2(acc[mt][j][2], acc[mt][j][3]);
        }
    }
}

__device__ __forceinline__ void store_f16_t(
    __half* __restrict__ Cf, size_t ldc, int row0, int col0,
    const float acc[2][8][4], float scale)
{
    const int lane = threadIdx.x & 31;
    const int warp = threadIdx.x >> 5;
    const int wm = warp >> 1, wn = warp & 1;
    #pragma unroll
    for (int mt = 0; mt < 2; mt++) {
        const int r = row0 + wm * 32 + mt * 16 + (lane >> 2);
        #pragma unroll
        for (int j = 0; j < 8; j++) {
            const int c = col0 + wn * 64 + j * 8 + (lane & 3) * 2;
            *(uint32_t*)(Cf + (size_t)r * ldc + c) =
                pack_h2(acc[mt][j][0] * scale, acc[mt][j][1] * scale);
            *(uint32_t*)(Cf + (size_t)(r + 8) * ldc + c) =
                pack_h2(acc[mt][j][2] * scale, acc[mt][j][3] * scale);
        }
    }
}

// Transposed fp16 V store via smem (128x128 tile)
#define VT_STRIDE 136
__device__ __forceinline__ void store_vt_f16(int row0, int col0, const float acc[2][8][4])
{
    extern __shared__ char dsm[];
    unsigned short* sp = (unsigned short*)dsm;
    const int tid  = threadIdx.x;
    const int lane = tid & 31;
    const int warp = tid >> 5;
    const int wm = warp >> 1, wn = warp & 1;

    #pragma unroll
    for (int mt = 0; mt < 2; mt++) {
        const int r = wm * 32 + mt * 16 + (lane >> 2);
        #pragma unroll
        for (int j = 0; j < 8; j++) {
            const int c = wn * 64 + j * 8 + (lane & 3) * 2;
            #pragma unroll
            for (int e = 0; e < 4; e++)
                sp[(r + (e >> 1) * 8) * VT_STRIDE + c + (e & 1)] =
                    hfu(__float2half_rn(acc[mt][j][e]));
        }
    }
    __syncthreads();

    const int b   = row0 >> 12;
    const int rin = row0 & (SEQ - 1);
    const int d   = tid >> 1;
    const int ks  = (tid & 1) * 64;
    __half* dst = g_Vtf + (size_t)b * D * SEQ + (size_t)(col0 + d) * SEQ + rin + ks;
    #pragma unroll
    for (int g = 0; g < 8; g++) {
        uint32_t w[4];
        #pragma unroll
        for (int h = 0; h < 4; h++) {
            uint32_t a0 = sp[(ks + g * 8 + h * 2) * VT_STRIDE + d];
            uint32_t a1 = sp[(ks + g * 8 + h * 2 + 1) * VT_STRIDE + d];
            w[h] = a0 | (a1 << 16);
        }
        *(uint4*)(dst + g * 8) = make_uint4(w[0], w[1], w[2], w[3]);
    }
}

// ===========================================================================
// Kernels
// ===========================================================================
__global__ void __launch_bounds__(256) cvt_kernel(const float* __restrict__ src,
                                                  __half* __restrict__ dst, int n)
{
    int i = (blockIdx.x * 256 + threadIdx.x) * 8;
    if (i >= n) return;
    float4 v0 = *(const float4*)(src + i);
    float4 v1 = *(const float4*)(src + i + 4);
    *(uint4*)(dst + i) = make_uint4(pack_h2(v0.x, v0.y), pack_h2(v0.z, v0.w),
                                    pack_h2(v1.x, v1.y), pack_h2(v1.z, v1.w));
}

// Q (z=0, pre-scaled) and K (z=1)
__global__ void __launch_bounds__(256, 2) qkv_qk()
{
    const int z    = blockIdx.z;
    const int row0 = blockIdx.y * 128;
    const int col0 = blockIdx.x * 128;

    float acc[2][8][4] = {};
    gemm_run_f(g_Xf + (size_t)row0 * D, D,
               g_Wf + (size_t)z * D * D + (size_t)col0 * D, D, D / 64, acc);

    if (z == 0) store_f16_t(g_Qf, D, row0, col0, acc, SCALE);
    else        store_f16_t(g_Kf, D, row0, col0, acc, 1.0f);
}

// V projection, stored transposed (runs concurrently with scores/softmax)
__global__ void __launch_bounds__(256, 2) qkv_v()
{
    const int row0 = blockIdx.y * 128;
    const int col0 = blockIdx.x * 128;

    float acc[2][8][4] = {};
    gemm_run_f(g_Xf + (size_t)row0 * D, D,
               g_Wf + (size_t)2 * D * D + (size_t)col0 * D, D, D / 64, acc);
    store_vt_f16(row0, col0, acc);
}

__global__ void __launch_bounds__(256, 2) scores_mm()
{
    const int t = blockIdx.x;
    int by = (int)((sqrtf(8.0f * t + 1.0f) - 1.0f) * 0.5f);
    while ((by + 1) * (by + 2) / 2 <= t) by++;
    while (by * (by + 1) / 2 > t) by--;
    const int bx = t - by * (by + 1) / 2;
    const int b  = blockIdx.y;
    const int row0 = by * 128, col0 = bx * 128;
    const size_t qoff = (size_t)b * SEQ * D;

    float acc[2][8][4] = {};
    gemm_run_f(g_Qf + qoff + (size_t)row0 * D, D,
               g_Kf + qoff + (size_t)col0 * D, D, D / 64, acc);
    store_f32_t(g_S + (size_t)b * SEQ * SEQ, SEQ, row0, col0, acc);
}

// Single-pass causal softmax; writes fp16 P zero-filled to 128 boundary.
__global__ void __launch_bounds__(256) softmax_kernel()
{
    __shared__ float srow[SEQ];
    __shared__ float red[256];
    const int q = blockIdx.x;
    const int b = blockIdx.y;
    const float* row = g_S + (size_t)b * SEQ * SEQ + (size_t)q * SEQ;
    const int len  = q + 1;
    const int wlen = ((q >> 7) + 1) << 7;
    const int tid  = threadIdx.x;

    float m = -INFINITY;
    for (int i = tid; i < len; i += 256) {
        float v = row[i];
        srow[i] = v;
        m = fmaxf(m, v);
    }
    red[tid] = m; __syncthreads();
    #pragma unroll
    for (int s = 128; s > 0; s >>= 1) {
        if (tid < s) red[tid] = fmaxf(red[tid], red[tid + s]);
        __syncthreads();
    }
    m = red[0]; __syncthreads();

    float sum = 0.0f;
    for (int i = tid; i < len; i += 256) {
        float e = __expf(srow[i] - m);
        srow[i] = e;
        sum += e;
    }
    red[tid] = sum; __syncthreads();
    #pragma unroll
    for (int s = 128; s > 0; s >>= 1) {
        if (tid < s) red[tid] += red[tid + s];
        __syncthreads();
    }
    const float inv = 1.0f / red[0];
    __syncthreads();

    __half* pf = g_Pf + (size_t)b * SEQ * SEQ + (size_t)q * SEQ;
    for (int i = tid; i < wlen; i += 256)
        pf[i] = (i < len) ? __float2half_rn(srow[i] * inv) : __float2half_rn(0.0f);
}

__global__ void __launch_bounds__(256, 2) pv_mm(float* __restrict__ Out)
{
    const int b    = blockIdx.z;
    const int by   = (gridDim.y - 1) - blockIdx.y;   // heavy rows first
    const int row0 = by * 128;
    const int col0 = blockIdx.x * 128;
    const int nchunks = (by + 1) * 2;                // Klim / 64

    const size_t poff = (size_t)b * SEQ * SEQ + (size_t)row0 * SEQ;
    const size_t voff = (size_t)b * D * SEQ + (size_t)col0 * SEQ;

    float acc[2][8][4] = {};
    gemm_run_f(g_Pf + poff, SEQ, g_Vtf + voff, SEQ, nchunks, acc);
    store_f32_t(Out + (size_t)b * SEQ * D, D, row0, col0, acc);
}

// ---------------------------------------------------------------------------
extern "C" void kernel_launch(void* const* d_in, const int* in_sizes, int n_in,
                              void* d_out, int out_size)
{
    const float* X  = (const float*)d_in[0];
    const float* Wq = (const float*)d_in[1];
    const float* Wk = (const float*)d_in[2];
    const float* Wv = (const float*)d_in[3];
    float* Out = (float*)d_out;

    // One-time host-side resources (no device memory involved)
    static cudaStream_t s2 = nullptr;
    static cudaEvent_t  evX = nullptr, evV = nullptr;
    static bool init_done = false;
    if (!init_done) {
        cudaStreamCreateWithFlags(&s2, cudaStreamNonBlocking);
        cudaEventCreateWithFlags(&evX, cudaEventDisableTiming);
        cudaEventCreateWithFlags(&evV, cudaEventDisableTiming);
        cudaFuncSetAttribute(qkv_qk,    cudaFuncAttributeMaxDynamicSharedMemorySize, DYN_F);
        cudaFuncSetAttribute(qkv_v,     cudaFuncAttributeMaxDynamicSharedMemorySize, DYN_F);
        cudaFuncSetAttribute(scores_mm, cudaFuncAttributeMaxDynamicSharedMemorySize, DYN_F);
        cudaFuncSetAttribute(pv_mm,     cudaFuncAttributeMaxDynamicSharedMemorySize, DYN_F);
        init_done = true;
    }

    __half *xf, *wf;
    cudaGetSymbolAddress((void**)&xf, g_Xf);
    cudaGetSymbolAddress((void**)&wf, g_Wf);

    // Main stream: X, Wq, Wk converts
    cvt_kernel<<<(NTOK * D) / 2048, 256>>>(X, xf, NTOK * D);
    cvt_kernel<<<(D * D) / 2048, 256>>>(Wq, wf + 0 * D * D, D * D);
    cvt_kernel<<<(D * D) / 2048, 256>>>(Wk, wf + 1 * D * D, D * D);
    cudaEventRecord(evX, 0);

    // Side stream: Wv convert + V projection (overlaps scores+softmax)
    cudaStreamWaitEvent(s2, evX, 0);
    cvt_kernel<<<(D * D) / 2048, 256, 0, s2>>>(Wv, wf + 2 * D * D, D * D);
    qkv_v<<<dim3(D / 128, NTOK / 128), 256, DYN_F, s2>>>();
    cudaEventRecord(evV, s2);

    // Main stream: Q,K projection -> scores -> softmax
    qkv_qk<<<dim3(D / 128, NTOK / 128, 2), 256, DYN_F>>>();
    scores_mm<<<dim3(528, BATCH), 256, DYN_F>>>();
    softmax_kernel<<<dim3(SEQ, BATCH), 256>>>();

    // Join V branch, then PV
    cudaStreamWaitEvent(0, evV, 0);
    pv_mm<<<dim3(D / 128, SEQ / 128, BATCH), 256, DYN_F>>>(Out);
}

// round 11
// speedup vs baseline: 1.2975x; 1.1011x over previous
#include <cuda_runtime.h>
#include <cuda_fp16.h>
#include <math.h>
#include <stdint.h>

#define D     768
#define SEQ   4096
#define BATCH 4
#define NTOK  (BATCH * SEQ)
#define SCALE 0.03608439182435161f  // 1/sqrt(768)

// ---------------------------------------------------------------------------
// Device-global scratch
// ---------------------------------------------------------------------------
__device__ __align__(256) __half g_Xf[NTOK * D];
__device__ __align__(256) __half g_Wf[3 * D * D];
__device__ __align__(256) __half g_Qf[NTOK * D];    // pre-scaled by SCALE
__device__ __align__(256) __half g_Kf[NTOK * D];
__device__ __align__(256) __half g_Vtf[NTOK * D];                 // [b][d][seq]
__device__ __align__(256) __half g_Ef[(size_t)BATCH * SEQ * SEQ]; // exp(S), fp16
__device__ float g_RS[(size_t)BATCH * 64 * SEQ];   // per-64col row partial sums
__device__ float g_InvSum[NTOK];                    // 1 / rowsum

// fp16 core: 128x64 tiles, stride 72 (144B rows, conflict-free ldmatrix)
#define FSTR     72
#define TILE_F   (128 * FSTR * 2)        // 18432 B
#define STAGE_F  (2 * TILE_F)            // A|B = 36864
#define NSTAGE   3
#define DYN_F    (NSTAGE * STAGE_F)      // 110592 (2 CTAs/SM)

// ---------------------------------------------------------------------------
// PTX helpers
// ---------------------------------------------------------------------------
__device__ __forceinline__ uint32_t smem_u32(const void* p) {
    uint32_t a;
    asm("{ .reg .u64 t; cvta.to.shared.u64 t, %1; cvt.u32.u64 %0, t; }" : "=r"(a) : "l"(p));
    return a;
}
__device__ __forceinline__ void ldsm4(uint32_t r[4], uint32_t addr) {
    asm volatile("ldmatrix.sync.aligned.m8n8.x4.shared.b16 {%0,%1,%2,%3}, [%4];"
                 : "=r"(r[0]), "=r"(r[1]), "=r"(r[2]), "=r"(r[3]) : "r"(addr));
}
__device__ __forceinline__ void mma_f16(float c[4], const uint32_t a[4],
                                        uint32_t b0, uint32_t b1) {
    asm volatile(
        "mma.sync.aligned.m16n8k16.row.col.f32.f16.f16.f32 "
        "{%0,%1,%2,%3}, {%4,%5,%6,%7}, {%8,%9}, {%0,%1,%2,%3};"
        : "+f"(c[0]), "+f"(c[1]), "+f"(c[2]), "+f"(c[3])
        : "r"(a[0]), "r"(a[1]), "r"(a[2]), "r"(a[3]), "r"(b0), "r"(b1));
}
#define CP16(dst, src) asm volatile("cp.async.cg.shared.global [%0], [%1], 16;" :: "r"(dst), "l"(src) : "memory")
#define CP_COMMIT()    asm volatile("cp.async.commit_group;" ::: "memory")
#define CP_WAIT0()     asm volatile("cp.async.wait_group 0;" ::: "memory")
#define CP_WAIT1()     asm volatile("cp.async.wait_group 1;" ::: "memory")

__device__ __forceinline__ unsigned short hfu(__half x) {
    return *reinterpret_cast<unsigned short*>(&x);
}
__device__ __forceinline__ uint32_t pack_h2(float v0, float v1) {
    return (uint32_t)hfu(__float2half_rn(v0)) | ((uint32_t)hfu(__float2half_rn(v1)) << 16);
}

// ===========================================================================
// fp16 single-mma 128x128 GEMM core, 256 threads, K-chunk 64, 3-stage pipe
// ===========================================================================
__device__ __forceinline__ void load_chunk_f(
    uint32_t stage,
    const __half* __restrict__ A, int lda,
    const __half* __restrict__ B, int ldb, int k0)
{
    const int t   = threadIdx.x;
    const int seg = t & 7;        // 16B segment of a 128B row (64 f16)
    const int r0  = t >> 3;       // 0..31
    #pragma unroll
    for (int i = 0; i < 4; i++) {
        const int row = r0 + i * 32;
        const uint32_t so = (uint32_t)(row * FSTR + seg * 8) * 2;
        CP16(stage + so,          A + (size_t)row * lda + k0 + seg * 8);
        CP16(stage + TILE_F + so, B + (size_t)row * ldb + k0 + seg * 8);
    }
}

__device__ __forceinline__ void compute_chunk_f(
    uint32_t stage, const uint32_t offA[2], const uint32_t offB[4],
    float acc[2][8][4])
{
    const uint32_t aT = stage, bT = stage + TILE_F;
    #pragma unroll
    for (int kk = 0; kk < 64; kk += 16) {
        uint32_t af[2][4];
        ldsm4(af[0], aT + offA[0] + kk * 2);
        ldsm4(af[1], aT + offA[1] + kk * 2);
        #pragma unroll
        for (int g = 0; g < 4; g++) {
            uint32_t bf[4];
            ldsm4(bf, bT + offB[g] + kk * 2);
            #pragma unroll
            for (int mt = 0; mt < 2; mt++) {
                #pragma unroll
                for (int nt = 0; nt < 2; nt++)
                    mma_f16(acc[mt][g * 2 + nt], af[mt], bf[nt * 2], bf[nt * 2 + 1]);
            }
        }
    }
}

__device__ __forceinline__ void gemm_run_f(
    const __half* __restrict__ A, int lda,
    const __half* __restrict__ B, int ldb,
    int nchunks, float acc[2][8][4])
{
    extern __shared__ char dsm[];
    const uint32_t base = smem_u32(dsm);
    const int lane = threadIdx.x & 31;
    const int warp = threadIdx.x >> 5;
    const int wm = warp >> 1, wn = warp & 1;
    const int rowA = ((lane >> 3) & 1) * 8 + (lane & 7);
    const int colA = (lane >> 4) * 8;
    const int rowB = (lane >> 4) * 8 + (lane & 7);
    const int colB = ((lane >> 3) & 1) * 8;

    uint32_t offA[2], offB[4];
    #pragma unroll
    for (int mt = 0; mt < 2; mt++)
        offA[mt] = ((wm * 32 + mt * 16 + rowA) * FSTR + colA) * 2;
    #pragma unroll
    for (int g = 0; g < 4; g++)
        offB[g] = ((wn * 64 + g * 16 + rowB) * FSTR + colB) * 2;

    // Prologue: stages 0 and 1 in flight
    load_chunk_f(base, A, lda, B, ldb, 0);
    CP_COMMIT();
    if (nchunks > 1) {
        load_chunk_f(base + STAGE_F, A, lda, B, ldb, 64);
        CP_COMMIT();
    }

    int s = 0;
    for (int c = 0; c < nchunks; c++) {
        if (c + 1 < nchunks) CP_WAIT1(); else CP_WAIT0();
        __syncthreads();
        if (c + 2 < nchunks) {
            int s2 = s + 2; if (s2 >= NSTAGE) s2 -= NSTAGE;
            load_chunk_f(base + s2 * STAGE_F, A, lda, B, ldb, (c + 2) * 64);
            CP_COMMIT();
        }
        compute_chunk_f(base + s * STAGE_F, offA, offB, acc);
        if (++s == NSTAGE) s = 0;
    }
    __syncthreads();
}

// ===========================================================================
// Epilogues (128x128, 8-warp 2x2 layout)
// ===========================================================================
// pv epilogue: per-row scale by inv row-sum
__device__ __forceinline__ void store_f32_rowscaled(
    float* __restrict__ C, size_t ldc, int row0, int col0,
    const float acc[2][8][4], const float* __restrict__ isum)
{
    const int lane = threadIdx.x & 31;
    const int warp = threadIdx.x >> 5;
    const int wm = warp >> 1, wn = warp & 1;
    #pragma unroll
    for (int mt = 0; mt < 2; mt++) {
        const int rt = wm * 32 + mt * 16 + (lane >> 2);
        const int r  = row0 + rt;
        const float i0 = isum[rt];
        const float i1 = isum[rt + 8];
        #pragma unroll
        for (int j = 0; j < 8; j++) {
            const int c = col0 + wn * 64 + j * 8 + (lane & 3) * 2;
            *(float2*)(C + (size_t)r * ldc + c) =
                make_float2(acc[mt][j][0] * i0, acc[mt][j][1] * i0);
            *(float2*)(C + (size_t)(r + 8) * ldc + c) =
                make_float2(acc[mt][j][2] * i1, acc[mt][j][3] * i1);
        }
    }
}

__device__ __forceinline__ void store_f16_t(
    __half* __restrict__ Cf, size_t ldc, int row0, int col0,
    const float acc[2][8][4], float scale)
{
    const int lane = threadIdx.x & 31;
    const int warp = threadIdx.x >> 5;
    const int wm = warp >> 1, wn = warp & 1;
    #pragma unroll
    for (int mt = 0; mt < 2; mt++) {
        const int r = row0 + wm * 32 + mt * 16 + (lane >> 2);
        #pragma unroll
        for (int j = 0; j < 8; j++) {
            const int c = col0 + wn * 64 + j * 8 + (lane & 3) * 2;
            *(uint32_t*)(Cf + (size_t)r * ldc + c) =
                pack_h2(acc[mt][j][0] * scale, acc[mt][j][1] * scale);
            *(uint32_t*)(Cf + (size_t)(r + 8) * ldc + c) =
                pack_h2(acc[mt][j][2] * scale, acc[mt][j][3] * scale);
        }
    }
}

// scores epilogue: E = exp(S) (fp16), causal mask on diagonal tiles, and
// deterministic per-row partial sums (64-col granularity) into g_RS.
__device__ __forceinline__ void store_exp_t(
    __half* __restrict__ Ef, int row0, int col0,
    const float acc[2][8][4], bool diag, int b, int bx)
{
    const int lane = threadIdx.x & 31;
    const int warp = threadIdx.x >> 5;
    const int wm = warp >> 1, wn = warp & 1;
    float* rs_base = g_RS + ((size_t)(b * 64 + bx * 2 + wn)) * SEQ + row0;

    #pragma unroll
    for (int mt = 0; mt < 2; mt++) {
        const int rt = wm * 32 + mt * 16 + (lane >> 2);   // tile-local row
        float rs0 = 0.0f, rs1 = 0.0f;
        #pragma unroll
        for (int j = 0; j < 8; j++) {
            const int ct = wn * 64 + j * 8 + (lane & 3) * 2;  // tile-local col
            float e0 = (!diag || ct     <= rt)     ? __expf(acc[mt][j][0]) : 0.0f;
            float e1 = (!diag || ct + 1 <= rt)     ? __expf(acc[mt][j][1]) : 0.0f;
            float e2 = (!diag || ct     <= rt + 8) ? __expf(acc[mt][j][2]) : 0.0f;
            float e3 = (!diag || ct + 1 <= rt + 8) ? __expf(acc[mt][j][3]) : 0.0f;
            *(uint32_t*)(Ef + (size_t)(row0 + rt) * SEQ + col0 + ct)     = pack_h2(e0, e1);
            *(uint32_t*)(Ef + (size_t)(row0 + rt + 8) * SEQ + col0 + ct) = pack_h2(e2, e3);
            rs0 += e0 + e1;
            rs1 += e2 + e3;
        }
        // deterministic fixed-tree reduction across the 4 lanes sharing a row
        rs0 += __shfl_xor_sync(0xFFFFFFFF, rs0, 1);
        rs0 += __shfl_xor_sync(0xFFFFFFFF, rs0, 2);
        rs1 += __shfl_xor_sync(0xFFFFFFFF, rs1, 1);
        rs1 += __shfl_xor_sync(0xFFFFFFFF, rs1, 2);
        if ((lane & 3) == 0) {
            rs_base[rt]     = rs0;
            rs_base[rt + 8] = rs1;
        }
    }
}

// Transposed fp16 V store via smem (128x128 tile)
#define VT_STRIDE 136
__device__ __forceinline__ void store_vt_f16(int row0, int col0, const float acc[2][8][4])
{
    extern __shared__ char dsm[];
    unsigned short* sp = (unsigned short*)dsm;
    const int tid  = threadIdx.x;
    const int lane = tid & 31;
    const int warp = tid >> 5;
    const int wm = warp >> 1, wn = warp & 1;

    #pragma unroll
    for (int mt = 0; mt < 2; mt++) {
        const int r = wm * 32 + mt * 16 + (lane >> 2);
        #pragma unroll
        for (int j = 0; j < 8; j++) {
            const int c = wn * 64 + j * 8 + (lane & 3) * 2;
            #pragma unroll
            for (int e = 0; e < 4; e++)
                sp[(r + (e >> 1) * 8) * VT_STRIDE + c + (e & 1)] =
                    hfu(__float2half_rn(acc[mt][j][e]));
        }
    }
    __syncthreads();

    const int b   = row0 >> 12;
    const int rin = row0 & (SEQ - 1);
    const int d   = tid >> 1;
    const int ks  = (tid & 1) * 64;
    __half* dst = g_Vtf + (size_t)b * D * SEQ + (size_t)(col0 + d) * SEQ + rin + ks;
    #pragma unroll
    for (int g = 0; g < 8; g++) {
        uint32_t w[4];
        #pragma unroll
        for (int h = 0; h < 4; h++) {
            uint32_t a0 = sp[(ks + g * 8 + h * 2) * VT_STRIDE + d];
            uint32_t a1 = sp[(ks + g * 8 + h * 2 + 1) * VT_STRIDE + d];
            w[h] = a0 | (a1 << 16);
        }
        *(uint4*)(dst + g * 8) = make_uint4(w[0], w[1], w[2], w[3]);
    }
}

// ===========================================================================
// Kernels
// ===========================================================================
__global__ void __launch_bounds__(256) cvt_kernel(const float* __restrict__ src,
                                                  __half* __restrict__ dst, int n)
{
    int i = (blockIdx.x * 256 + threadIdx.x) * 8;
    if (i >= n) return;
    float4 v0 = *(const float4*)(src + i);
    float4 v1 = *(const float4*)(src + i + 4);
    *(uint4*)(dst + i) = make_uint4(pack_h2(v0.x, v0.y), pack_h2(v0.z, v0.w),
                                    pack_h2(v1.x, v1.y), pack_h2(v1.z, v1.w));
}

// Q (z=0, pre-scaled) and K (z=1)
__global__ void __launch_bounds__(256, 2) qkv_qk()
{
    const int z    = blockIdx.z;
    const int row0 = blockIdx.y * 128;
    const int col0 = blockIdx.x * 128;

    float acc[2][8][4] = {};
    gemm_run_f(g_Xf + (size_t)row0 * D, D,
               g_Wf + (size_t)z * D * D + (size_t)col0 * D, D, D / 64, acc);

    if (z == 0) store_f16_t(g_Qf, D, row0, col0, acc, SCALE);
    else        store_f16_t(g_Kf, D, row0, col0, acc, 1.0f);
}

// V projection, stored transposed (runs concurrently with scores)
__global__ void __launch_bounds__(256, 2) qkv_v()
{
    const int row0 = blockIdx.y * 128;
    const int col0 = blockIdx.x * 128;

    float acc[2][8][4] = {};
    gemm_run_f(g_Xf + (size_t)row0 * D, D,
               g_Wf + (size_t)2 * D * D + (size_t)col0 * D, D, D / 64, acc);
    store_vt_f16(row0, col0, acc);
}

// S tile -> exp -> fp16 E + row partial sums (no separate softmax kernel)
__global__ void __launch_bounds__(256, 2) scores_mm()
{
    const int t = blockIdx.x;
    int by = (int)((sqrtf(8.0f * t + 1.0f) - 1.0f) * 0.5f);
    while ((by + 1) * (by + 2) / 2 <= t) by++;
    while (by * (by + 1) / 2 > t) by--;
    const int bx = t - by * (by + 1) / 2;
    const int b  = blockIdx.y;
    const int row0 = by * 128, col0 = bx * 128;
    const size_t qoff = (size_t)b * SEQ * D;

    float acc[2][8][4] = {};
    gemm_run_f(g_Qf + qoff + (size_t)row0 * D, D,
               g_Kf + qoff + (size_t)col0 * D, D, D / 64, acc);
    store_exp_t(g_Ef + (size_t)b * SEQ * SEQ, row0, col0, acc, by == bx, b, bx);
}

// Sum the <=64 deterministic partials per row -> 1/rowsum
__global__ void __launch_bounds__(256) rowsum_kernel()
{
    const int g = blockIdx.x * 256 + threadIdx.x;
    if (g >= NTOK) return;
    const int b = g >> 12;
    const int q = g & (SEQ - 1);
    const int n = ((q >> 7) + 1) * 2;
    const float* rs = g_RS + ((size_t)b * 64) * SEQ + q;
    float s = 0.0f;
    for (int i = 0; i < n; i++) s += rs[(size_t)i * SEQ];
    g_InvSum[g] = 1.0f / s;
}

__global__ void __launch_bounds__(256, 2) pv_mm(float* __restrict__ Out)
{
    const int b    = blockIdx.z;
    const int by   = (gridDim.y - 1) - blockIdx.y;   // heavy rows first
    const int row0 = by * 128;
    const int col0 = blockIdx.x * 128;
    const int nchunks = (by + 1) * 2;                // Klim / 64

    const size_t poff = (size_t)b * SEQ * SEQ + (size_t)row0 * SEQ;
    const size_t voff = (size_t)b * D * SEQ + (size_t)col0 * SEQ;

    float acc[2][8][4] = {};
    gemm_run_f(g_Ef + poff, SEQ, g_Vtf + voff, SEQ, nchunks, acc);
    store_f32_rowscaled(Out + (size_t)b * SEQ * D, D, row0, col0, acc,
                        g_InvSum + b * SEQ + row0);
}

// ---------------------------------------------------------------------------
extern "C" void kernel_launch(void* const* d_in, const int* in_sizes, int n_in,
                              void* d_out, int out_size)
{
    const float* X  = (const float*)d_in[0];
    const float* Wq = (const float*)d_in[1];
    const float* Wk = (const float*)d_in[2];
    const float* Wv = (const float*)d_in[3];
    float* Out = (float*)d_out;

    // One-time host-side resources (no device memory involved)
    static cudaStream_t s2 = nullptr;
    static cudaEvent_t  evX = nullptr, evV = nullptr;
    static bool init_done = false;
    if (!init_done) {
        cudaStreamCreateWithFlags(&s2, cudaStreamNonBlocking);
        cudaEventCreateWithFlags(&evX, cudaEventDisableTiming);
        cudaEventCreateWithFlags(&evV, cudaEventDisableTiming);
        cudaFuncSetAttribute(qkv_qk,    cudaFuncAttributeMaxDynamicSharedMemorySize, DYN_F);
        cudaFuncSetAttribute(qkv_v,     cudaFuncAttributeMaxDynamicSharedMemorySize, DYN_F);
        cudaFuncSetAttribute(scores_mm, cudaFuncAttributeMaxDynamicSharedMemorySize, DYN_F);
        cudaFuncSetAttribute(pv_mm,     cudaFuncAttributeMaxDynamicSharedMemorySize, DYN_F);
        init_done = true;
    }

    __half *xf, *wf;
    cudaGetSymbolAddress((void**)&xf, g_Xf);
    cudaGetSymbolAddress((void**)&wf, g_Wf);

    // Main stream: X, Wq, Wk converts
    cvt_kernel<<<(NTOK * D) / 2048, 256>>>(X, xf, NTOK * D);
    cvt_kernel<<<(D * D) / 2048, 256>>>(Wq, wf + 0 * D * D, D * D);
    cvt_kernel<<<(D * D) / 2048, 256>>>(Wk, wf + 1 * D * D, D * D);
    cudaEventRecord(evX, 0);

    // Side stream: Wv convert + V projection (overlaps scores)
    cudaStreamWaitEvent(s2, evX, 0);
    cvt_kernel<<<(D * D) / 2048, 256, 0, s2>>>(Wv, wf + 2 * D * D, D * D);
    qkv_v<<<dim3(D / 128, NTOK / 128), 256, DYN_F, s2>>>();
    cudaEventRecord(evV, s2);

    // Main stream: Q,K projection -> scores(+exp+partials) -> rowsum
    qkv_qk<<<dim3(D / 128, NTOK / 128, 2), 256, DYN_F>>>();
    scores_mm<<<dim3(528, BATCH), 256, DYN_F>>>();
    rowsum_kernel<<<NTOK / 256, 256>>>();

    // Join V branch, then PV (deferred normalization in epilogue)
    cudaStreamWaitEvent(0, evV, 0);
    pv_mm<<<dim3(D / 128, SEQ / 128, BATCH), 256, DYN_F>>>(Out);
}

// round 12
// speedup vs baseline: 1.3118x; 1.0110x over previous
#include <cuda_runtime.h>
#include <cuda_fp16.h>
#include <math.h>
#include <stdint.h>

#define D     768
#define SEQ   4096
#define BATCH 4
#define NTOK  (BATCH * SEQ)
#define SCALE 0.03608439182435161f  // 1/sqrt(768)

// ---------------------------------------------------------------------------
// Device-global scratch
// ---------------------------------------------------------------------------
__device__ __align__(256) __half g_Xf[NTOK * D];
__device__ __align__(256) __half g_Wf[3 * D * D];
__device__ __align__(256) __half g_Qf[NTOK * D];    // pre-scaled by SCALE
__device__ __align__(256) __half g_Kf[NTOK * D];
__device__ __align__(256) __half g_Vtf[NTOK * D];                 // [b][d][seq]
__device__ __align__(256) __half g_Ef[(size_t)BATCH * SEQ * SEQ]; // exp(S), fp16
__device__ float g_RS[(size_t)BATCH * 64 * SEQ];   // per-64col row partial sums

// fp16 core: 128x64 tiles, stride 72 (144B rows, conflict-free ldmatrix)
#define FSTR     72
#define TILE_F   (128 * FSTR * 2)        // 18432 B
#define STAGE_F  (2 * TILE_F)            // A|B = 36864
#define NSTAGE   3
#define DYN_F    (NSTAGE * STAGE_F)      // 110592 (2 CTAs/SM)

// ---------------------------------------------------------------------------
// PTX helpers
// ---------------------------------------------------------------------------
__device__ __forceinline__ uint32_t smem_u32(const void* p) {
    uint32_t a;
    asm("{ .reg .u64 t; cvta.to.shared.u64 t, %1; cvt.u32.u64 %0, t; }" : "=r"(a) : "l"(p));
    return a;
}
__device__ __forceinline__ void ldsm4(uint32_t r[4], uint32_t addr) {
    asm volatile("ldmatrix.sync.aligned.m8n8.x4.shared.b16 {%0,%1,%2,%3}, [%4];"
                 : "=r"(r[0]), "=r"(r[1]), "=r"(r[2]), "=r"(r[3]) : "r"(addr));
}
__device__ __forceinline__ void mma_f16(float c[4], const uint32_t a[4],
                                        uint32_t b0, uint32_t b1) {
    asm volatile(
        "mma.sync.aligned.m16n8k16.row.col.f32.f16.f16.f32 "
        "{%0,%1,%2,%3}, {%4,%5,%6,%7}, {%8,%9}, {%0,%1,%2,%3};"
        : "+f"(c[0]), "+f"(c[1]), "+f"(c[2]), "+f"(c[3])
        : "r"(a[0]), "r"(a[1]), "r"(a[2]), "r"(a[3]), "r"(b0), "r"(b1));
}
#define CP16(dst, src) asm volatile("cp.async.cg.shared.global [%0], [%1], 16;" :: "r"(dst), "l"(src) : "memory")
#define CP_COMMIT()    asm volatile("cp.async.commit_group;" ::: "memory")
#define CP_WAIT0()     asm volatile("cp.async.wait_group 0;" ::: "memory")
#define CP_WAIT1()     asm volatile("cp.async.wait_group 1;" ::: "memory")

__device__ __forceinline__ unsigned short hfu(__half x) {
    return *reinterpret_cast<unsigned short*>(&x);
}
__device__ __forceinline__ uint32_t pack_h2(float v0, float v1) {
    return (uint32_t)hfu(__float2half_rn(v0)) | ((uint32_t)hfu(__float2half_rn(v1)) << 16);
}

// ===========================================================================
// fp16 single-mma 128x128 GEMM core, 256 threads, K-chunk 64, 3-stage pipe
// ===========================================================================
__device__ __forceinline__ void load_chunk_f(
    uint32_t stage,
    const __half* __restrict__ A, int lda,
    const __half* __restrict__ B, int ldb, int k0)
{
    const int t   = threadIdx.x;
    const int seg = t & 7;        // 16B segment of a 128B row (64 f16)
    const int r0  = t >> 3;       // 0..31
    #pragma unroll
    for (int i = 0; i < 4; i++) {
        const int row = r0 + i * 32;
        const uint32_t so = (uint32_t)(row * FSTR + seg * 8) * 2;
        CP16(stage + so,          A + (size_t)row * lda + k0 + seg * 8);
        CP16(stage + TILE_F + so, B + (size_t)row * ldb + k0 + seg * 8);
    }
}

__device__ __forceinline__ void compute_chunk_f(
    uint32_t stage, const uint32_t offA[2], const uint32_t offB[4],
    float acc[2][8][4])
{
    const uint32_t aT = stage, bT = stage + TILE_F;
    #pragma unroll
    for (int kk = 0; kk < 64; kk += 16) {
        uint32_t af[2][4];
        ldsm4(af[0], aT + offA[0] + kk * 2);
        ldsm4(af[1], aT + offA[1] + kk * 2);
        #pragma unroll
        for (int g = 0; g < 4; g++) {
            uint32_t bf[4];
            ldsm4(bf, bT + offB[g] + kk * 2);
            #pragma unroll
            for (int mt = 0; mt < 2; mt++) {
                #pragma unroll
                for (int nt = 0; nt < 2; nt++)
                    mma_f16(acc[mt][g * 2 + nt], af[mt], bf[nt * 2], bf[nt * 2 + 1]);
            }
        }
    }
}

__device__ __forceinline__ void gemm_run_f(
    const __half* __restrict__ A, int lda,
    const __half* __restrict__ B, int ldb,
    int nchunks, float acc[2][8][4])
{
    extern __shared__ char dsm[];
    const uint32_t base = smem_u32(dsm);
    const int lane = threadIdx.x & 31;
    const int warp = threadIdx.x >> 5;
    const int wm = warp >> 1, wn = warp & 1;
    const int rowA = ((lane >> 3) & 1) * 8 + (lane & 7);
    const int colA = (lane >> 4) * 8;
    const int rowB = (lane >> 4) * 8 + (lane & 7);
    const int colB = ((lane >> 3) & 1) * 8;

    uint32_t offA[2], offB[4];
    #pragma unroll
    for (int mt = 0; mt < 2; mt++)
        offA[mt] = ((wm * 32 + mt * 16 + rowA) * FSTR + colA) * 2;
    #pragma unroll
    for (int g = 0; g < 4; g++)
        offB[g] = ((wn * 64 + g * 16 + rowB) * FSTR + colB) * 2;

    // Prologue: stages 0 and 1 in flight
    load_chunk_f(base, A, lda, B, ldb, 0);
    CP_COMMIT();
    if (nchunks > 1) {
        load_chunk_f(base + STAGE_F, A, lda, B, ldb, 64);
        CP_COMMIT();
    }

    int s = 0;
    for (int c = 0; c < nchunks; c++) {
        if (c + 1 < nchunks) CP_WAIT1(); else CP_WAIT0();
        __syncthreads();
        if (c + 2 < nchunks) {
            int s2 = s + 2; if (s2 >= NSTAGE) s2 -= NSTAGE;
            load_chunk_f(base + s2 * STAGE_F, A, lda, B, ldb, (c + 2) * 64);
            CP_COMMIT();
        }
        compute_chunk_f(base + s * STAGE_F, offA, offB, acc);
        if (++s == NSTAGE) s = 0;
    }
    __syncthreads();
}

// ===========================================================================
// Epilogues (128x128, 8-warp 2x2 layout)
// ===========================================================================
// pv epilogue: per-row scale by inv row-sum (from smem)
__device__ __forceinline__ void store_f32_rowscaled(
    float* __restrict__ C, size_t ldc, int row0, int col0,
    const float acc[2][8][4], const float* __restrict__ isum)
{
    const int lane = threadIdx.x & 31;
    const int warp = threadIdx.x >> 5;
    const int wm = warp >> 1, wn = warp & 1;
    #pragma unroll
    for (int mt = 0; mt < 2; mt++) {
        const int rt = wm * 32 + mt * 16 + (lane >> 2);
        const int r  = row0 + rt;
        const float i0 = isum[rt];
        const float i1 = isum[rt + 8];
        #pragma unroll
        for (int j = 0; j < 8; j++) {
            const int c = col0 + wn * 64 + j * 8 + (lane & 3) * 2;
            *(float2*)(C + (size_t)r * ldc + c) =
                make_float2(acc[mt][j][0] * i0, acc[mt][j][1] * i0);
            *(float2*)(C + (size_t)(r + 8) * ldc + c) =
                make_float2(acc[mt][j][2] * i1, acc[mt][j][3] * i1);
        }
    }
}

__device__ __forceinline__ void store_f16_t(
    __half* __restrict__ Cf, size_t ldc, int row0, int col0,
    const float acc[2][8][4], float scale)
{
    const int lane = threadIdx.x & 31;
    const int warp = threadIdx.x >> 5;
    const int wm = warp >> 1, wn = warp & 1;
    #pragma unroll
    for (int mt = 0; mt < 2; mt++) {
        const int r = row0 + wm * 32 + mt * 16 + (lane >> 2);
        #pragma unroll
        for (int j = 0; j < 8; j++) {
            const int c = col0 + wn * 64 + j * 8 + (lane & 3) * 2;
            *(uint32_t*)(Cf + (size_t)r * ldc + c) =
                pack_h2(acc[mt][j][0] * scale, acc[mt][j][1] * scale);
            *(uint32_t*)(Cf + (size_t)(r + 8) * ldc + c) =
                pack_h2(acc[mt][j][2] * scale, acc[mt][j][3] * scale);
        }
    }
}

// scores epilogue: E = exp(S) (fp16), causal mask on diagonal tiles, and
// deterministic per-row partial sums (64-col granularity) into g_RS.
__device__ __forceinline__ void store_exp_t(
    __half* __restrict__ Ef, int row0, int col0,
    const float acc[2][8][4], bool diag, int b, int bx)
{
    const int lane = threadIdx.x & 31;
    const int warp = threadIdx.x >> 5;
    const int wm = warp >> 1, wn = warp & 1;
    float* rs_base = g_RS + ((size_t)(b * 64 + bx * 2 + wn)) * SEQ + row0;

    #pragma unroll
    for (int mt = 0; mt < 2; mt++) {
        const int rt = wm * 32 + mt * 16 + (lane >> 2);   // tile-local row
        float rs0 = 0.0f, rs1 = 0.0f;
        #pragma unroll
        for (int j = 0; j < 8; j++) {
            const int ct = wn * 64 + j * 8 + (lane & 3) * 2;  // tile-local col
            float e0 = (!diag || ct     <= rt)     ? __expf(acc[mt][j][0]) : 0.0f;
            float e1 = (!diag || ct + 1 <= rt)     ? __expf(acc[mt][j][1]) : 0.0f;
            float e2 = (!diag || ct     <= rt + 8) ? __expf(acc[mt][j][2]) : 0.0f;
            float e3 = (!diag || ct + 1 <= rt + 8) ? __expf(acc[mt][j][3]) : 0.0f;
            *(uint32_t*)(Ef + (size_t)(row0 + rt) * SEQ + col0 + ct)     = pack_h2(e0, e1);
            *(uint32_t*)(Ef + (size_t)(row0 + rt + 8) * SEQ + col0 + ct) = pack_h2(e2, e3);
            rs0 += e0 + e1;
            rs1 += e2 + e3;
        }
        rs0 += __shfl_xor_sync(0xFFFFFFFF, rs0, 1);
        rs0 += __shfl_xor_sync(0xFFFFFFFF, rs0, 2);
        rs1 += __shfl_xor_sync(0xFFFFFFFF, rs1, 1);
        rs1 += __shfl_xor_sync(0xFFFFFFFF, rs1, 2);
        if ((lane & 3) == 0) {
            rs_base[rt]     = rs0;
            rs_base[rt + 8] = rs1;
        }
    }
}

// Transposed fp16 V store via smem (128x128 tile)
#define VT_STRIDE 136
__device__ __forceinline__ void store_vt_f16(int row0, int col0, const float acc[2][8][4])
{
    extern __shared__ char dsm[];
    unsigned short* sp = (unsigned short*)dsm;
    const int tid  = threadIdx.x;
    const int lane = tid & 31;
    const int warp = tid >> 5;
    const int wm = warp >> 1, wn = warp & 1;

    #pragma unroll
    for (int mt = 0; mt < 2; mt++) {
        const int r = wm * 32 + mt * 16 + (lane >> 2);
        #pragma unroll
        for (int j = 0; j < 8; j++) {
            const int c = wn * 64 + j * 8 + (lane & 3) * 2;
            #pragma unroll
            for (int e = 0; e < 4; e++)
                sp[(r + (e >> 1) * 8) * VT_STRIDE + c + (e & 1)] =
                    hfu(__float2half_rn(acc[mt][j][e]));
        }
    }
    __syncthreads();

    const int b   = row0 >> 12;
    const int rin = row0 & (SEQ - 1);
    const int d   = tid >> 1;
    const int ks  = (tid & 1) * 64;
    __half* dst = g_Vtf + (size_t)b * D * SEQ + (size_t)(col0 + d) * SEQ + rin + ks;
    #pragma unroll
    for (int g = 0; g < 8; g++) {
        uint32_t w[4];
        #pragma unroll
        for (int h = 0; h < 4; h++) {
            uint32_t a0 = sp[(ks + g * 8 + h * 2) * VT_STRIDE + d];
            uint32_t a1 = sp[(ks + g * 8 + h * 2 + 1) * VT_STRIDE + d];
            w[h] = a0 | (a1 << 16);
        }
        *(uint4*)(dst + g * 8) = make_uint4(w[0], w[1], w[2], w[3]);
    }
}

// ===========================================================================
// Kernels
// ===========================================================================
__global__ void __launch_bounds__(256) cvt_kernel(const float* __restrict__ src,
                                                  __half* __restrict__ dst, int n)
{
    int i = (blockIdx.x * 256 + threadIdx.x) * 8;
    if (i >= n) return;
    float4 v0 = *(const float4*)(src + i);
    float4 v1 = *(const float4*)(src + i + 4);
    *(uint4*)(dst + i) = make_uint4(pack_h2(v0.x, v0.y), pack_h2(v0.z, v0.w),
                                    pack_h2(v1.x, v1.y), pack_h2(v1.z, v1.w));
}

// All three weight matrices in one launch (z selects Wq/Wk/Wv)
__global__ void __launch_bounds__(256) cvtw_kernel(const float* __restrict__ wq,
                                                   const float* __restrict__ wk,
                                                   const float* __restrict__ wv)
{
    const float* src = (blockIdx.z == 0) ? wq : (blockIdx.z == 1) ? wk : wv;
    __half* dst = g_Wf + (size_t)blockIdx.z * D * D;
    int i = (blockIdx.x * 256 + threadIdx.x) * 8;
    float4 v0 = *(const float4*)(src + i);
    float4 v1 = *(const float4*)(src + i + 4);
    *(uint4*)(dst + i) = make_uint4(pack_h2(v0.x, v0.y), pack_h2(v0.z, v0.w),
                                    pack_h2(v1.x, v1.y), pack_h2(v1.z, v1.w));
}

// Q (z=0, pre-scaled), K (z=1), V transposed (z=2)
__global__ void __launch_bounds__(256, 2) qkv_mm()
{
    const int z    = blockIdx.z;
    const int row0 = blockIdx.y * 128;
    const int col0 = blockIdx.x * 128;

    float acc[2][8][4] = {};
    gemm_run_f(g_Xf + (size_t)row0 * D, D,
               g_Wf + (size_t)z * D * D + (size_t)col0 * D, D, D / 64, acc);

    if (z == 0)      store_f16_t(g_Qf, D, row0, col0, acc, SCALE);
    else if (z == 1) store_f16_t(g_Kf, D, row0, col0, acc, 1.0f);
    else             store_vt_f16(row0, col0, acc);
}

// S tile -> exp -> fp16 E + row partial sums
__global__ void __launch_bounds__(256, 2) scores_mm()
{
    const int t = blockIdx.x;
    int by = (int)((sqrtf(8.0f * t + 1.0f) - 1.0f) * 0.5f);
    while ((by + 1) * (by + 2) / 2 <= t) by++;
    while (by * (by + 1) / 2 > t) by--;
    const int bx = t - by * (by + 1) / 2;
    const int b  = blockIdx.y;
    const int row0 = by * 128, col0 = bx * 128;
    const size_t qoff = (size_t)b * SEQ * D;

    float acc[2][8][4] = {};
    gemm_run_f(g_Qf + qoff + (size_t)row0 * D, D,
               g_Kf + qoff + (size_t)col0 * D, D, D / 64, acc);
    store_exp_t(g_Ef + (size_t)b * SEQ * SEQ, row0, col0, acc, by == bx, b, bx);
}

// PV with rowsum folded into the epilogue (deterministic fixed-order sums)
__global__ void __launch_bounds__(256, 2) pv_mm(float* __restrict__ Out)
{
    extern __shared__ char dsm[];
    const int b    = blockIdx.z;
    const int by   = (gridDim.y - 1) - blockIdx.y;   // heavy rows first
    const int row0 = by * 128;
    const int col0 = blockIdx.x * 128;
    const int nchunks = (by + 1) * 2;                // Klim / 64

    const size_t poff = (size_t)b * SEQ * SEQ + (size_t)row0 * SEQ;
    const size_t voff = (size_t)b * D * SEQ + (size_t)col0 * SEQ;

    float acc[2][8][4] = {};
    gemm_run_f(g_Ef + poff, SEQ, g_Vtf + voff, SEQ, nchunks, acc);

    // inline rowsum: thread t<128 handles row row0+t (fixed order, deterministic)
    float* s_inv = (float*)dsm;      // gemm_run_f ended with __syncthreads()
    if (threadIdx.x < 128) {
        const float* rs = g_RS + ((size_t)b * 64) * SEQ + row0 + threadIdx.x;
        float s = 0.0f;
        for (int i = 0; i < nchunks; i++) s += rs[(size_t)i * SEQ];
        s_inv[threadIdx.x] = 1.0f / s;
    }
    __syncthreads();

    store_f32_rowscaled(Out + (size_t)b * SEQ * D, D, row0, col0, acc, s_inv);
}

// ---------------------------------------------------------------------------
extern "C" void kernel_launch(void* const* d_in, const int* in_sizes, int n_in,
                              void* d_out, int out_size)
{
    const float* X  = (const float*)d_in[0];
    const float* Wq = (const float*)d_in[1];
    const float* Wk = (const float*)d_in[2];
    const float* Wv = (const float*)d_in[3];
    float* Out = (float*)d_out;

    static bool init_done = false;
    if (!init_done) {
        cudaFuncSetAttribute(qkv_mm,    cudaFuncAttributeMaxDynamicSharedMemorySize, DYN_F);
        cudaFuncSetAttribute(scores_mm, cudaFuncAttributeMaxDynamicSharedMemorySize, DYN_F);
        cudaFuncSetAttribute(pv_mm,     cudaFuncAttributeMaxDynamicSharedMemorySize, DYN_F);
        init_done = true;
    }

    __half* xf;
    cudaGetSymbolAddress((void**)&xf, g_Xf);

    cvt_kernel<<<(NTOK * D) / 2048, 256>>>(X, xf, NTOK * D);
    cvtw_kernel<<<dim3((D * D) / 2048, 1, 3), 256>>>(Wq, Wk, Wv);

    qkv_mm<<<dim3(D / 128, NTOK / 128, 3), 256, DYN_F>>>();
    scores_mm<<<dim3(528, BATCH), 256, DYN_F>>>();
    pv_mm<<<dim3(D / 128, SEQ / 128, BATCH), 256, DYN_F>>>(Out);
}

// round 13
// speedup vs baseline: 1.3140x; 1.0017x over previous
#include <cuda_runtime.h>
#include <cuda_fp16.h>
#include <math.h>
#include <stdint.h>

#define D     768
#define SEQ   4096
#define BATCH 4
#define NTOK  (BATCH * SEQ)
#define SCALE 0.03608439182435161f  // 1/sqrt(768)

// ---------------------------------------------------------------------------
// Device-global scratch
// ---------------------------------------------------------------------------
__device__ __align__(256) __half g_Xf[NTOK * D];
__device__ __align__(256) __half g_Wf[3 * D * D];
__device__ __align__(256) __half g_Qf[NTOK * D];    // pre-scaled by SCALE
__device__ __align__(256) __half g_Kf[NTOK * D];
__device__ __align__(256) __half g_Vtf[NTOK * D];                 // [b][d][seq]
__device__ __align__(256) __half g_Ef[(size_t)BATCH * SEQ * SEQ]; // exp(S), fp16
__device__ float g_RS[(size_t)BATCH * 64 * SEQ];   // per-64col row partial sums

// fp16 core: 128x64 tiles, stride 72 (144B rows, conflict-free ldmatrix)
#define FSTR     72
#define TILE_F   (128 * FSTR * 2)        // 18432 B
#define STAGE_F  (2 * TILE_F)            // A|B = 36864
#define NSTAGE   3
#define DYN_F    (NSTAGE * STAGE_F)      // 110592 (2 CTAs/SM)

// ---------------------------------------------------------------------------
// PTX helpers
// ---------------------------------------------------------------------------
__device__ __forceinline__ uint32_t smem_u32(const void* p) {
    uint32_t a;
    asm("{ .reg .u64 t; cvta.to.shared.u64 t, %1; cvt.u32.u64 %0, t; }" : "=r"(a) : "l"(p));
    return a;
}
__device__ __forceinline__ void ldsm4(uint32_t r[4], uint32_t addr) {
    asm volatile("ldmatrix.sync.aligned.m8n8.x4.shared.b16 {%0,%1,%2,%3}, [%4];"
                 : "=r"(r[0]), "=r"(r[1]), "=r"(r[2]), "=r"(r[3]) : "r"(addr));
}
__device__ __forceinline__ void mma_f16(float c[4], const uint32_t a[4],
                                        uint32_t b0, uint32_t b1) {
    asm volatile(
        "mma.sync.aligned.m16n8k16.row.col.f32.f16.f16.f32 "
        "{%0,%1,%2,%3}, {%4,%5,%6,%7}, {%8,%9}, {%0,%1,%2,%3};"
        : "+f"(c[0]), "+f"(c[1]), "+f"(c[2]), "+f"(c[3])
        : "r"(a[0]), "r"(a[1]), "r"(a[2]), "r"(a[3]), "r"(b0), "r"(b1));
}
#define CP16(dst, src) asm volatile("cp.async.cg.shared.global [%0], [%1], 16;" :: "r"(dst), "l"(src) : "memory")
#define CP_COMMIT()    asm volatile("cp.async.commit_group;" ::: "memory")
#define CP_WAIT0()     asm volatile("cp.async.wait_group 0;" ::: "memory")
#define CP_WAIT1()     asm volatile("cp.async.wait_group 1;" ::: "memory")

__device__ __forceinline__ unsigned short hfu(__half x) {
    return *reinterpret_cast<unsigned short*>(&x);
}
__device__ __forceinline__ uint32_t pack_h2(float v0, float v1) {
    return (uint32_t)hfu(__float2half_rn(v0)) | ((uint32_t)hfu(__float2half_rn(v1)) << 16);
}

// ===========================================================================
// fp16 single-mma 128x128 GEMM core, 256 threads, K-chunk 64, 3-stage pipe
// ===========================================================================
__device__ __forceinline__ void load_chunk_f(
    uint32_t stage,
    const __half* __restrict__ A, int lda,
    const __half* __restrict__ B, int ldb, int k0)
{
    const int t   = threadIdx.x;
    const int seg = t & 7;        // 16B segment of a 128B row (64 f16)
    const int r0  = t >> 3;       // 0..31
    #pragma unroll
    for (int i = 0; i < 4; i++) {
        const int row = r0 + i * 32;
        const uint32_t so = (uint32_t)(row * FSTR + seg * 8) * 2;
        CP16(stage + so,          A + (size_t)row * lda + k0 + seg * 8);
        CP16(stage + TILE_F + so, B + (size_t)row * ldb + k0 + seg * 8);
    }
}

// Software-pipelined: every ldsm issues >=1 group (4 mma) ahead of its use.
// Fragment ring buffers sized to keep register count at the old 24.
__device__ __forceinline__ void compute_chunk_f(
    uint32_t stage, const uint32_t offA[2], const uint32_t offB[4],
    float acc[2][8][4])
{
    const uint32_t aT = stage, bT = stage + TILE_F;
    uint32_t af[2][2][4];   // [kk ring][mt][4]
    uint32_t bf[2][4];      // [group ring][4]

    ldsm4(af[0][0], aT + offA[0]);
    ldsm4(af[0][1], aT + offA[1]);
    ldsm4(bf[0],    bT + offB[0]);

    #pragma unroll
    for (int ki = 0; ki < 4; ki++) {              // kk = ki*16
        const int cur = ki & 1, nxt = cur ^ 1;
        const uint32_t ko  = (uint32_t)(ki * 16) * 2;
        const uint32_t kon = (uint32_t)(ki * 16 + 16) * 2;
        #pragma unroll
        for (int g = 0; g < 4; g++) {
            // prefetch B for next group (or next kk's group 0)
            if (g < 3)
                ldsm4(bf[(g + 1) & 1], bT + offB[g + 1] + ko);
            else if (ki < 3)
                ldsm4(bf[0], bT + offB[0] + kon);
            // prefetch A for next kk in early group slots
            if (ki < 3) {
                if (g == 0) ldsm4(af[nxt][0], aT + offA[0] + kon);
                if (g == 1) ldsm4(af[nxt][1], aT + offA[1] + kon);
            }
            const uint32_t* b = bf[g & 1];
            #pragma unroll
            for (int mt = 0; mt < 2; mt++) {
                mma_f16(acc[mt][g * 2 + 0], af[cur][mt], b[0], b[1]);
                mma_f16(acc[mt][g * 2 + 1], af[cur][mt], b[2], b[3]);
            }
        }
    }
}

__device__ __forceinline__ void gemm_run_f(
    const __half* __restrict__ A, int lda,
    const __half* __restrict__ B, int ldb,
    int nchunks, float acc[2][8][4])
{
    extern __shared__ char dsm[];
    const uint32_t base = smem_u32(dsm);
    const int lane = threadIdx.x & 31;
    const int warp = threadIdx.x >> 5;
    const int wm = warp >> 1, wn = warp & 1;
    const int rowA = ((lane >> 3) & 1) * 8 + (lane & 7);
    const int colA = (lane >> 4) * 8;
    const int rowB = (lane >> 4) * 8 + (lane & 7);
    const int colB = ((lane >> 3) & 1) * 8;

    uint32_t offA[2], offB[4];
    #pragma unroll
    for (int mt = 0; mt < 2; mt++)
        offA[mt] = ((wm * 32 + mt * 16 + rowA) * FSTR + colA) * 2;
    #pragma unroll
    for (int g = 0; g < 4; g++)
        offB[g] = ((wn * 64 + g * 16 + rowB) * FSTR + colB) * 2;

    // Prologue: stages 0 and 1 in flight
    load_chunk_f(base, A, lda, B, ldb, 0);
    CP_COMMIT();
    if (nchunks > 1) {
        load_chunk_f(base + STAGE_F, A, lda, B, ldb, 64);
        CP_COMMIT();
    }

    int s = 0;
    for (int c = 0; c < nchunks; c++) {
        if (c + 1 < nchunks) CP_WAIT1(); else CP_WAIT0();
        __syncthreads();
        if (c + 2 < nchunks) {
            int s2 = s + 2; if (s2 >= NSTAGE) s2 -= NSTAGE;
            load_chunk_f(base + s2 * STAGE_F, A, lda, B, ldb, (c + 2) * 64);
            CP_COMMIT();
        }
        compute_chunk_f(base + s * STAGE_F, offA, offB, acc);
        if (++s == NSTAGE) s = 0;
    }
    __syncthreads();
}

// ===========================================================================
// Epilogues (128x128, 8-warp 2x2 layout)
// ===========================================================================
// pv epilogue: per-row scale by inv row-sum (from smem)
__device__ __forceinline__ void store_f32_rowscaled(
    float* __restrict__ C, size_t ldc, int row0, int col0,
    const float acc[2][8][4], const float* __restrict__ isum)
{
    const int lane = threadIdx.x & 31;
    const int warp = threadIdx.x >> 5;
    const int wm = warp >> 1, wn = warp & 1;
    #pragma unroll
    for (int mt = 0; mt < 2; mt++) {
        const int rt = wm * 32 + mt * 16 + (lane >> 2);
        const int r  = row0 + rt;
        const float i0 = isum[rt];
        const float i1 = isum[rt + 8];
        #pragma unroll
        for (int j = 0; j < 8; j++) {
            const int c = col0 + wn * 64 + j * 8 + (lane & 3) * 2;
            *(float2*)(C + (size_t)r * ldc + c) =
                make_float2(acc[mt][j][0] * i0, acc[mt][j][1] * i0);
            *(float2*)(C + (size_t)(r + 8) * ldc + c) =
                make_float2(acc[mt][j][2] * i1, acc[mt][j][3] * i1);
        }
    }
}

__device__ __forceinline__ void store_f16_t(
    __half* __restrict__ Cf, size_t ldc, int row0, int col0,
    const float acc[2][8][4], float scale)
{
    const int lane = threadIdx.x & 31;
    const int warp = threadIdx.x >> 5;
    const int wm = warp >> 1, wn = warp & 1;
    #pragma unroll
    for (int mt = 0; mt < 2; mt++) {
        const int r = row0 + wm * 32 + mt * 16 + (lane >> 2);
        #pragma unroll
        for (int j = 0; j < 8; j++) {
            const int c = col0 + wn * 64 + j * 8 + (lane & 3) * 2;
            *(uint32_t*)(Cf + (size_t)r * ldc + c) =
                pack_h2(acc[mt][j][0] * scale, acc[mt][j][1] * scale);
            *(uint32_t*)(Cf + (size_t)(r + 8) * ldc + c) =
                pack_h2(acc[mt][j][2] * scale, acc[mt][j][3] * scale);
        }
    }
}

// scores epilogue: E = exp(S) (fp16), causal mask on diagonal tiles, and
// deterministic per-row partial sums (64-col granularity) into g_RS.
__device__ __forceinline__ void store_exp_t(
    __half* __restrict__ Ef, int row0, int col0,
    const float acc[2][8][4], bool diag, int b, int bx)
{
    const int lane = threadIdx.x & 31;
    const int warp = threadIdx.x >> 5;
    const int wm = warp >> 1, wn = warp & 1;
    float* rs_base = g_RS + ((size_t)(b * 64 + bx * 2 + wn)) * SEQ + row0;

    #pragma unroll
    for (int mt = 0; mt < 2; mt++) {
        const int rt = wm * 32 + mt * 16 + (lane >> 2);   // tile-local row
        float rs0 = 0.0f, rs1 = 0.0f;
        #pragma unroll
        for (int j = 0; j < 8; j++) {
            const int ct = wn * 64 + j * 8 + (lane & 3) * 2;  // tile-local col
            float e0 = (!diag || ct     <= rt)     ? __expf(acc[mt][j][0]) : 0.0f;
            float e1 = (!diag || ct + 1 <= rt)     ? __expf(acc[mt][j][1]) : 0.0f;
            float e2 = (!diag || ct     <= rt + 8) ? __expf(acc[mt][j][2]) : 0.0f;
            float e3 = (!diag || ct + 1 <= rt + 8) ? __expf(acc[mt][j][3]) : 0.0f;
            *(uint32_t*)(Ef + (size_t)(row0 + rt) * SEQ + col0 + ct)     = pack_h2(e0, e1);
            *(uint32_t*)(Ef + (size_t)(row0 + rt + 8) * SEQ + col0 + ct) = pack_h2(e2, e3);
            rs0 += e0 + e1;
            rs1 += e2 + e3;
        }
        rs0 += __shfl_xor_sync(0xFFFFFFFF, rs0, 1);
        rs0 += __shfl_xor_sync(0xFFFFFFFF, rs0, 2);
        rs1 += __shfl_xor_sync(0xFFFFFFFF, rs1, 1);
        rs1 += __shfl_xor_sync(0xFFFFFFFF, rs1, 2);
        if ((lane & 3) == 0) {
            rs_base[rt]     = rs0;
            rs_base[rt + 8] = rs1;
        }
    }
}

// Transposed fp16 V store via smem (128x128 tile)
#define VT_STRIDE 136
__device__ __forceinline__ void store_vt_f16(int row0, int col0, const float acc[2][8][4])
{
    extern __shared__ char dsm[];
    unsigned short* sp = (unsigned short*)dsm;
    const int tid  = threadIdx.x;
    const int lane = tid & 31;
    const int warp = tid >> 5;
    const int wm = warp >> 1, wn = warp & 1;

    #pragma unroll
    for (int mt = 0; mt < 2; mt++) {
        const int r = wm * 32 + mt * 16 + (lane >> 2);
        #pragma unroll
        for (int j = 0; j < 8; j++) {
            const int c = wn * 64 + j * 8 + (lane & 3) * 2;
            #pragma unroll
            for (int e = 0; e < 4; e++)
                sp[(r + (e >> 1) * 8) * VT_STRIDE + c + (e & 1)] =
                    hfu(__float2half_rn(acc[mt][j][e]));
        }
    }
    __syncthreads();

    const int b   = row0 >> 12;
    const int rin = row0 & (SEQ - 1);
    const int d   = tid >> 1;
    const int ks  = (tid & 1) * 64;
    __half* dst = g_Vtf + (size_t)b * D * SEQ + (size_t)(col0 + d) * SEQ + rin + ks;
    #pragma unroll
    for (int g = 0; g < 8; g++) {
        uint32_t w[4];
        #pragma unroll
        for (int h = 0; h < 4; h++) {
            uint32_t a0 = sp[(ks + g * 8 + h * 2) * VT_STRIDE + d];
            uint32_t a1 = sp[(ks + g * 8 + h * 2 + 1) * VT_STRIDE + d];
            w[h] = a0 | (a1 << 16);
        }
        *(uint4*)(dst + g * 8) = make_uint4(w[0], w[1], w[2], w[3]);
    }
}

// ===========================================================================
// Kernels
// ===========================================================================
__global__ void __launch_bounds__(256) cvt_kernel(const float* __restrict__ src,
                                                  __half* __restrict__ dst, int n)
{
    int i = (blockIdx.x * 256 + threadIdx.x) * 8;
    if (i >= n) return;
    float4 v0 = *(const float4*)(src + i);
    float4 v1 = *(const float4*)(src + i + 4);
    *(uint4*)(dst + i) = make_uint4(pack_h2(v0.x, v0.y), pack_h2(v0.z, v0.w),
                                    pack_h2(v1.x, v1.y), pack_h2(v1.z, v1.w));
}

// All three weight matrices in one launch (z selects Wq/Wk/Wv)
__global__ void __launch_bounds__(256) cvtw_kernel(const float* __restrict__ wq,
                                                   const float* __restrict__ wk,
                                                   const float* __restrict__ wv)
{
    const float* src = (blockIdx.z == 0) ? wq : (blockIdx.z == 1) ? wk : wv;
    __half* dst = g_Wf + (size_t)blockIdx.z * D * D;
    int i = (blockIdx.x * 256 + threadIdx.x) * 8;
    float4 v0 = *(const float4*)(src + i);
    float4 v1 = *(const float4*)(src + i + 4);
    *(uint4*)(dst + i) = make_uint4(pack_h2(v0.x, v0.y), pack_h2(v0.z, v0.w),
                                    pack_h2(v1.x, v1.y), pack_h2(v1.z, v1.w));
}

// Q (z=0, pre-scaled), K (z=1), V transposed (z=2)
__global__ void __launch_bounds__(256, 2) qkv_mm()
{
    const int z    = blockIdx.z;
    const int row0 = blockIdx.y * 128;
    const int col0 = blockIdx.x * 128;

    float acc[2][8][4] = {};
    gemm_run_f(g_Xf + (size_t)row0 * D, D,
               g_Wf + (size_t)z * D * D + (size_t)col0 * D, D, D / 64, acc);

    if (z == 0)      store_f16_t(g_Qf, D, row0, col0, acc, SCALE);
    else if (z == 1) store_f16_t(g_Kf, D, row0, col0, acc, 1.0f);
    else             store_vt_f16(row0, col0, acc);
}

// S tile -> exp -> fp16 E + row partial sums
__global__ void __launch_bounds__(256, 2) scores_mm()
{
    const int t = blockIdx.x;
    int by = (int)((sqrtf(8.0f * t + 1.0f) - 1.0f) * 0.5f);
    while ((by + 1) * (by + 2) / 2 <= t) by++;
    while (by * (by + 1) / 2 > t) by--;
    const int bx = t - by * (by + 1) / 2;
    const int b  = blockIdx.y;
    const int row0 = by * 128, col0 = bx * 128;
    const size_t qoff = (size_t)b * SEQ * D;

    float acc[2][8][4] = {};
    gemm_run_f(g_Qf + qoff + (size_t)row0 * D, D,
               g_Kf + qoff + (size_t)col0 * D, D, D / 64, acc);
    store_exp_t(g_Ef + (size_t)b * SEQ * SEQ, row0, col0, acc, by == bx, b, bx);
}

// PV with rowsum folded into the epilogue (deterministic fixed-order sums)
__global__ void __launch_bounds__(256, 2) pv_mm(float* __restrict__ Out)
{
    extern __shared__ char dsm[];
    const int b    = blockIdx.z;
    const int by   = (gridDim.y - 1) - blockIdx.y;   // heavy rows first
    const int row0 = by * 128;
    const int col0 = blockIdx.x * 128;
    const int nchunks = (by + 1) * 2;                // Klim / 64

    const size_t poff = (size_t)b * SEQ * SEQ + (size_t)row0 * SEQ;
    const size_t voff = (size_t)b * D * SEQ + (size_t)col0 * SEQ;

    float acc[2][8][4] = {};
    gemm_run_f(g_Ef + poff, SEQ, g_Vtf + voff, SEQ, nchunks, acc);

    // inline rowsum: thread t<128 handles row row0+t (fixed order, deterministic)
    float* s_inv = (float*)dsm;      // gemm_run_f ended with __syncthreads()
    if (threadIdx.x < 128) {
        const float* rs = g_RS + ((size_t)b * 64) * SEQ + row0 + threadIdx.x;
        float s = 0.0f;
        for (int i = 0; i < nchunks; i++) s += rs[(size_t)i * SEQ];
        s_inv[threadIdx.x] = 1.0f / s;
    }
    __syncthreads();

    store_f32_rowscaled(Out + (size_t)b * SEQ * D, D, row0, col0, acc, s_inv);
}

// ---------------------------------------------------------------------------
extern "C" void kernel_launch(void* const* d_in, const int* in_sizes, int n_in,
                              void* d_out, int out_size)
{
    const float* X  = (const float*)d_in[0];
    const float* Wq = (const float*)d_in[1];
    const float* Wk = (const float*)d_in[2];
    const float* Wv = (const float*)d_in[3];
    float* Out = (float*)d_out;

    static bool init_done = false;
    if (!init_done) {
        cudaFuncSetAttribute(qkv_mm,    cudaFuncAttributeMaxDynamicSharedMemorySize, DYN_F);
        cudaFuncSetAttribute(scores_mm, cudaFuncAttributeMaxDynamicSharedMemorySize, DYN_F);
        cudaFuncSetAttribute(pv_mm,     cudaFuncAttributeMaxDynamicSharedMemorySize, DYN_F);
        init_done = true;
    }

    __half* xf;
    cudaGetSymbolAddress((void**)&xf, g_Xf);

    cvt_kernel<<<(NTOK * D) / 2048, 256>>>(X, xf, NTOK * D);
    cvtw_kernel<<<dim3((D * D) / 2048, 1, 3), 256>>>(Wq, Wk, Wv);

    qkv_mm<<<dim3(D / 128, NTOK / 128, 3), 256, DYN_F>>>();
    scores_mm<<<dim3(528, BATCH), 256, DYN_F>>>();
    pv_mm<<<dim3(D / 128, SEQ / 128, BATCH), 256, DYN_F>>>(Out);
}